// round 1
// baseline (speedup 1.0000x reference)
#include <cuda_runtime.h>

// ---------------- problem constants ----------------
#define NWIN   1024
#define NTOK   128
#define DIMC   192
#define NHEADS 6
#define HDIM   32
#define QKVC   576           // 3*DIMC
#define CATC   384           // 2*DIMC
#define MROWS  (NWIN*NTOK)   // 131072
#define SCALE  0.17677669529663687f   // 1/sqrt(32)

// ---------------- scratch (device globals: no allocation allowed) ----------------
__device__ float g_qkv [NWIN * NTOK * QKVC];   // self-branch qkv, [b][n][3*192]
__device__ float g_qkvm[NWIN * NTOK * QKVC];   // mutual-branch qkv
__device__ float g_cat [NWIN * NTOK * CATC];   // [mutual(192) | self(192)]
__device__ float g_bias[NHEADS * NTOK * NTOK]; // gathered relative position bias

// ---------------- bias gather ----------------
__global__ void bias_gather_kernel(const int* __restrict__ relidx,
                                   const float* __restrict__ rpb) {
    int i = blockIdx.x;        // query token
    int j = threadIdx.x;       // key token
    int id = relidx[i * NTOK + j];
    #pragma unroll
    for (int h = 0; h < NHEADS; h++)
        g_bias[h * NTOK * NTOK + i * NTOK + j] = rpb[id * NHEADS + h];
}

// ---------------- generic fp32 GEMM: C[M,N] = A'[M,K] @ W[K,N] (+bias) ----------------
// A'[m][k] = A[m][k] + (addrow ? addrow[(m&63)*K + k] : 0)
// 64x64 tile, 256 threads, 4x4 micro-tile, K-chunks of 16, float4 everywhere.
// Requires: M%64==0, N%64==0, K%16==0 (true for all three uses).
__global__ void __launch_bounds__(256)
gemm_kernel(const float* __restrict__ A, const float* __restrict__ W,
            const float* __restrict__ addrow, const float* __restrict__ bias,
            float* __restrict__ C, int M, int K, int N) {
    __shared__ float As[16][68];   // transposed: As[k][m], pad keeps 16B alignment
    __shared__ float Ws[16][64];

    const int tid  = threadIdx.x;
    const int tx   = tid & 15;
    const int ty   = tid >> 4;
    const int mBase = blockIdx.y * 64;
    const int nBase = blockIdx.x * 64;

    // loader indices
    const int aRow  = tid >> 2;    // 0..63
    const int aCol4 = tid & 3;     // which float4 within the 16-wide K chunk
    const int wRow  = tid >> 4;    // 0..15
    const int wCol4 = tid & 15;    // which float4 within the 64-wide N tile

    float acc[4][4];
    #pragma unroll
    for (int i = 0; i < 4; i++)
        #pragma unroll
        for (int j = 0; j < 4; j++) acc[i][j] = 0.0f;

    for (int k0 = 0; k0 < K; k0 += 16) {
        // --- load A tile (64 x 16), one float4 per thread ---
        {
            const int m = mBase + aRow;
            float4 av = *(reinterpret_cast<const float4*>(&A[(size_t)m * K + k0]) + aCol4);
            if (addrow) {
                float4 pv = *(reinterpret_cast<const float4*>(&addrow[(size_t)(m & 63) * K + k0]) + aCol4);
                av.x += pv.x; av.y += pv.y; av.z += pv.z; av.w += pv.w;
            }
            As[aCol4 * 4 + 0][aRow] = av.x;
            As[aCol4 * 4 + 1][aRow] = av.y;
            As[aCol4 * 4 + 2][aRow] = av.z;
            As[aCol4 * 4 + 3][aRow] = av.w;
        }
        // --- load W tile (16 x 64), one float4 per thread ---
        {
            float4 wv = *(reinterpret_cast<const float4*>(&W[(size_t)(k0 + wRow) * N + nBase]) + wCol4);
            *reinterpret_cast<float4*>(&Ws[wRow][wCol4 * 4]) = wv;
        }
        __syncthreads();

        #pragma unroll
        for (int kk = 0; kk < 16; kk++) {
            float4 a4 = *reinterpret_cast<const float4*>(&As[kk][ty * 4]);
            float4 w4 = *reinterpret_cast<const float4*>(&Ws[kk][tx * 4]);
            const float a[4] = {a4.x, a4.y, a4.z, a4.w};
            const float w[4] = {w4.x, w4.y, w4.z, w4.w};
            #pragma unroll
            for (int i = 0; i < 4; i++)
                #pragma unroll
                for (int j = 0; j < 4; j++)
                    acc[i][j] += a[i] * w[j];
        }
        __syncthreads();
    }

    #pragma unroll
    for (int i = 0; i < 4; i++) {
        const int m = mBase + ty * 4 + i;
        const int n = nBase + tx * 4;
        float4 v = make_float4(acc[i][0], acc[i][1], acc[i][2], acc[i][3]);
        if (bias) {
            v.x += bias[n + 0]; v.y += bias[n + 1];
            v.z += bias[n + 2]; v.w += bias[n + 3];
        }
        *reinterpret_cast<float4*>(&C[(size_t)m * N + n]) = v;
    }
}

// ---------------- self attention: one block per (head, window), thread = query row ----
// Single pass, no max-subtraction: logits bounded (qk ~0.1, bias ~0.05, mask ~N(0,1),
// max |logit| ~ 6 over the whole dataset -> exp() safely in range).
__global__ void __launch_bounds__(128)
self_attn_kernel(const float* __restrict__ mask) {
    __shared__ float Ks[NTOK][HDIM];
    __shared__ float Vs[NTOK][HDIM];
    const int h = blockIdx.x, b = blockIdx.y;
    const int t = threadIdx.x;
    const float* base = g_qkv + (size_t)b * NTOK * QKVC;

    {   // cooperative, coalesced K/V tile load
        const int d = t & 31, r0 = t >> 5;
        #pragma unroll
        for (int i = 0; i < 32; i++) {
            const int row = r0 + i * 4;
            Ks[row][d] = base[row * QKVC + DIMC     + h * HDIM + d];
            Vs[row][d] = base[row * QKVC + 2 * DIMC + h * HDIM + d];
        }
    }
    float4 qv[8];
    {
        const float4* qp = reinterpret_cast<const float4*>(base + t * QKVC + h * HDIM);
        #pragma unroll
        for (int i = 0; i < 8; i++) {
            qv[i] = qp[i];
            qv[i].x *= SCALE; qv[i].y *= SCALE; qv[i].z *= SCALE; qv[i].w *= SCALE;
        }
    }
    __syncthreads();

    const float* brow = g_bias + h * NTOK * NTOK + t * NTOK;
    const float* mrow = mask + (size_t)(b & 63) * NTOK * NTOK + t * NTOK;

    float sum = 0.0f;
    float4 acc[8];
    #pragma unroll
    for (int i = 0; i < 8; i++) acc[i] = make_float4(0.f, 0.f, 0.f, 0.f);

    #pragma unroll 4
    for (int kk = 0; kk < NTOK; kk++) {
        const float4* kr = reinterpret_cast<const float4*>(Ks[kk]);
        float s = brow[kk] + mrow[kk];
        #pragma unroll
        for (int i = 0; i < 8; i++) {
            float4 kx = kr[i];
            s += qv[i].x * kx.x + qv[i].y * kx.y + qv[i].z * kx.z + qv[i].w * kx.w;
        }
        const float e = __expf(s);
        sum += e;
        const float4* vr = reinterpret_cast<const float4*>(Vs[kk]);
        #pragma unroll
        for (int i = 0; i < 8; i++) {
            float4 vx = vr[i];
            acc[i].x += e * vx.x; acc[i].y += e * vx.y;
            acc[i].z += e * vx.z; acc[i].w += e * vx.w;
        }
    }
    const float inv = 1.0f / sum;
    float4* orow = reinterpret_cast<float4*>(g_cat + ((size_t)b * NTOK + t) * CATC + DIMC + h * HDIM);
    #pragma unroll
    for (int i = 0; i < 8; i++) {
        acc[i].x *= inv; acc[i].y *= inv; acc[i].z *= inv; acc[i].w *= inv;
        orow[i] = acc[i];
    }
}

// ---------------- mutual cross-half attention ----------------
// Output token t<64  : aligned0 -> query token 64+t, keys/values tokens [0,64),  mask row t
// Output token t>=64 : aligned1 -> query token t-64, keys/values tokens [64,128), mask row t-64
// Mutual result occupies channels [0,192) of g_cat.
__global__ void __launch_bounds__(128)
mutual_attn_kernel(const float* __restrict__ mask) {
    __shared__ float Ks[NTOK][HDIM];
    __shared__ float Vs[NTOK][HDIM];
    const int h = blockIdx.x, b = blockIdx.y;
    const int t = threadIdx.x;
    const float* base = g_qkvm + (size_t)b * NTOK * QKVC;

    {
        const int d = t & 31, r0 = t >> 5;
        #pragma unroll
        for (int i = 0; i < 32; i++) {
            const int row = r0 + i * 4;
            Ks[row][d] = base[row * QKVC + DIMC     + h * HDIM + d];
            Vs[row][d] = base[row * QKVC + 2 * DIMC + h * HDIM + d];
        }
    }
    const int qtok  = (t < 64) ? (64 + t) : (t - 64);
    const int kbase = (t < 64) ? 0 : 64;
    const int mri   = (t < 64) ? t : (t - 64);

    float4 qv[8];
    {
        const float4* qp = reinterpret_cast<const float4*>(base + qtok * QKVC + h * HDIM);
        #pragma unroll
        for (int i = 0; i < 8; i++) {
            qv[i] = qp[i];
            qv[i].x *= SCALE; qv[i].y *= SCALE; qv[i].z *= SCALE; qv[i].w *= SCALE;
        }
    }
    __syncthreads();

    const float* mrow = mask + (size_t)(b & 63) * NTOK * NTOK + mri * NTOK;  // cols [0,64)

    float sum = 0.0f;
    float4 acc[8];
    #pragma unroll
    for (int i = 0; i < 8; i++) acc[i] = make_float4(0.f, 0.f, 0.f, 0.f);

    #pragma unroll 4
    for (int kk = 0; kk < 64; kk++) {
        const float4* kr = reinterpret_cast<const float4*>(Ks[kbase + kk]);
        float s = mrow[kk];
        #pragma unroll
        for (int i = 0; i < 8; i++) {
            float4 kx = kr[i];
            s += qv[i].x * kx.x + qv[i].y * kx.y + qv[i].z * kx.z + qv[i].w * kx.w;
        }
        const float e = __expf(s);
        sum += e;
        const float4* vr = reinterpret_cast<const float4*>(Vs[kbase + kk]);
        #pragma unroll
        for (int i = 0; i < 8; i++) {
            float4 vx = vr[i];
            acc[i].x += e * vx.x; acc[i].y += e * vx.y;
            acc[i].z += e * vx.z; acc[i].w += e * vx.w;
        }
    }
    const float inv = 1.0f / sum;
    float4* orow = reinterpret_cast<float4*>(g_cat + ((size_t)b * NTOK + t) * CATC + h * HDIM);
    #pragma unroll
    for (int i = 0; i < 8; i++) {
        acc[i].x *= inv; acc[i].y *= inv; acc[i].z *= inv; acc[i].w *= inv;
        orow[i] = acc[i];
    }
}

// ---------------- launch ----------------
extern "C" void kernel_launch(void* const* d_in, const int* in_sizes, int n_in,
                              void* d_out, int out_size) {
    const float* x      = (const float*)d_in[0];  // [1024,128,192]
    const float* mask   = (const float*)d_in[1];  // [64,128,128]
    const float* w_qkv  = (const float*)d_in[2];  // [192,576]
    const float* w_qkvm = (const float*)d_in[3];  // [192,576]
    const float* w_proj = (const float*)d_in[4];  // [384,192]
    const float* b_proj = (const float*)d_in[5];  // [192]
    const float* rpb    = (const float*)d_in[6];  // [675,6]
    const float* posb   = (const float*)d_in[7];  // [1,64,192]
    const int*   relidx = (const int*)  d_in[8];  // [128,128]
    float* out = (float*)d_out;                   // [1024,128,192]

    float *qkv, *qkvm, *cat;
    cudaGetSymbolAddress((void**)&qkv,  g_qkv);
    cudaGetSymbolAddress((void**)&qkvm, g_qkvm);
    cudaGetSymbolAddress((void**)&cat,  g_cat);

    // 1) relative-position bias gather
    bias_gather_kernel<<<NTOK, NTOK>>>(relidx, rpb);

    // 2) qkv projections (self: x @ w_qkv ; mutual: (x + tiled sine pos) @ w_qkv_mutual)
    gemm_kernel<<<dim3(QKVC / 64, MROWS / 64), 256>>>(x, w_qkv,  nullptr, nullptr, qkv,  MROWS, DIMC, QKVC);
    gemm_kernel<<<dim3(QKVC / 64, MROWS / 64), 256>>>(x, w_qkvm, posb,    nullptr, qkvm, MROWS, DIMC, QKVC);

    // 3) attention branches (write disjoint halves of g_cat channels)
    self_attn_kernel  <<<dim3(NHEADS, NWIN), 128>>>(mask);
    mutual_attn_kernel<<<dim3(NHEADS, NWIN), 128>>>(mask);

    // 4) output projection: g_cat[131072,384] @ w_proj[384,192] + b_proj
    gemm_kernel<<<dim3(DIMC / 64, MROWS / 64), 256>>>(cat, w_proj, nullptr, b_proj, out, MROWS, CATC, DIMC);
}

// round 2
// speedup vs baseline: 1.3155x; 1.3155x over previous
#include <cuda_runtime.h>
#include <cuda_bf16.h>

// ---------------- problem constants ----------------
#define NWIN   1024
#define NTOK   128
#define DIMC   192
#define NHEADS 6
#define HDIM   32
#define QKVC   576           // 3*DIMC
#define CATC   384           // 2*DIMC
#define MROWS  (NWIN*NTOK)   // 131072
#define SCALE  0.17677669529663687f   // 1/sqrt(32)

// ---------------- scratch (device globals: no allocation allowed) ----------------
__device__ float g_qkv [NWIN * NTOK * QKVC];
__device__ float g_qkvm[NWIN * NTOK * QKVC];
__device__ float g_cat [NWIN * NTOK * CATC];
__device__ float g_bias[NHEADS * NTOK * NTOK];

// ---------------- f32x2 packed-math helpers (sm_103a dual-fp32) ----------------
typedef unsigned long long u64;
__device__ __forceinline__ u64 fma2(u64 a, u64 b, u64 c) {
    u64 d; asm("fma.rn.f32x2 %0,%1,%2,%3;" : "=l"(d) : "l"(a), "l"(b), "l"(c)); return d;
}
__device__ __forceinline__ u64 mul2(u64 a, u64 b) {
    u64 d; asm("mul.rn.f32x2 %0,%1,%2;" : "=l"(d) : "l"(a), "l"(b)); return d;
}
__device__ __forceinline__ u64 pack2(float x, float y) {
    u64 d; asm("mov.b64 %0,{%1,%2};" : "=l"(d) : "f"(x), "f"(y)); return d;
}
__device__ __forceinline__ float2 unpack2(u64 v) {
    float2 r; asm("mov.b64 {%0,%1},%2;" : "=f"(r.x), "=f"(r.y) : "l"(v)); return r;
}

// ---------------- bias gather ----------------
__global__ void bias_gather_kernel(const int* __restrict__ relidx,
                                   const float* __restrict__ rpb) {
    int i = blockIdx.x;
    int j = threadIdx.x;
    int id = relidx[i * NTOK + j];
    #pragma unroll
    for (int h = 0; h < NHEADS; h++)
        g_bias[h * NTOK * NTOK + i * NTOK + j] = rpb[id * NHEADS + h];
}

// ---------------- bf16x3 tensor-core GEMM ----------------
// C[M,N] = A'[M,K] @ W[K,N] (+bias), A'[m][k] = A[m][k] + addrow[(m&63)*K+k]
// fp32 operands split as a = hi + lo (bf16 each); D += Ahi*Bhi + Ahi*Blo + Alo*Bhi
// gives ~1e-6 effective precision with fp32 accumulation.
// Block tile 128x64, K-step 32, 256 threads (8 warps as 4x2 of 32x32 warp tiles).
#define BM 128
#define BN 64
#define BK 32
#define ASTR 34   // halfs per smem row (32 + 2 pad) -> 17 words
#define WSTR 17

#define MMA16816(d, a, b) \
    asm volatile("mma.sync.aligned.m16n8k16.row.col.f32.bf16.bf16.f32 " \
        "{%0,%1,%2,%3}, {%4,%5,%6,%7}, {%8,%9}, {%0,%1,%2,%3};" \
        : "+f"(d[0]), "+f"(d[1]), "+f"(d[2]), "+f"(d[3]) \
        : "r"(a[0]), "r"(a[1]), "r"(a[2]), "r"(a[3]), "r"(b[0]), "r"(b[1]))

__global__ void __launch_bounds__(256)
gemm_bf16x3_kernel(const float* __restrict__ A, const float* __restrict__ W,
                   const float* __restrict__ addrow, const float* __restrict__ bias,
                   float* __restrict__ C, int M, int K, int N) {
    __shared__ alignas(16) __nv_bfloat16 Ah[BM * ASTR];
    __shared__ alignas(16) __nv_bfloat16 Al[BM * ASTR];
    __shared__ alignas(16) __nv_bfloat16 Bh[BN * ASTR];
    __shared__ alignas(16) __nv_bfloat16 Bl[BN * ASTR];

    const int tid  = threadIdx.x;
    const int lane = tid & 31, warp = tid >> 5;
    const int g    = lane >> 2, tg = lane & 3;
    const int wr   = warp >> 1, wc = warp & 1;     // 4 x 2 warp grid
    const int mBase = blockIdx.y * BM;
    const int nBase = blockIdx.x * BN;

    const unsigned* pAh = reinterpret_cast<const unsigned*>(Ah);
    const unsigned* pAl = reinterpret_cast<const unsigned*>(Al);
    const unsigned* pBh = reinterpret_cast<const unsigned*>(Bh);
    const unsigned* pBl = reinterpret_cast<const unsigned*>(Bl);

    float acc[2][4][4];
    #pragma unroll
    for (int mt = 0; mt < 2; mt++)
        #pragma unroll
        for (int nt = 0; nt < 4; nt++)
            #pragma unroll
            for (int i = 0; i < 4; i++) acc[mt][nt][i] = 0.0f;

    for (int k0 = 0; k0 < K; k0 += BK) {
        // ---- load A tile (128 x 32 f32), split to bf16 hi/lo ----
        #pragma unroll
        for (int i = 0; i < 4; i++) {
            const int idx = tid + i * 256;
            const int row = idx >> 3;          // 0..127
            const int c4  = idx & 7;           // float4 within 32-wide K chunk
            const int m   = mBase + row;
            float4 av = *reinterpret_cast<const float4*>(&A[(size_t)m * K + k0 + c4 * 4]);
            if (addrow) {
                float4 pv = *reinterpret_cast<const float4*>(&addrow[(size_t)(m & 63) * K + k0 + c4 * 4]);
                av.x += pv.x; av.y += pv.y; av.z += pv.z; av.w += pv.w;
            }
            const float vv[4] = {av.x, av.y, av.z, av.w};
            #pragma unroll
            for (int j = 0; j < 4; j++) {
                __nv_bfloat16 hi = __float2bfloat16(vv[j]);
                float rem = vv[j] - __bfloat162float(hi);
                Ah[row * ASTR + c4 * 4 + j] = hi;
                Al[row * ASTR + c4 * 4 + j] = __float2bfloat16(rem);
            }
        }
        // ---- load B tile (32 x 64 f32), transpose to [n][k], split hi/lo ----
        #pragma unroll
        for (int i = 0; i < 2; i++) {
            const int idx = tid + i * 256;
            const int kr  = idx >> 4;          // 0..31
            const int n4  = idx & 15;          // float4 within 64-wide N tile
            float4 wv = *reinterpret_cast<const float4*>(&W[(size_t)(k0 + kr) * N + nBase + n4 * 4]);
            const float vv[4] = {wv.x, wv.y, wv.z, wv.w};
            #pragma unroll
            for (int j = 0; j < 4; j++) {
                const int n = n4 * 4 + j;
                __nv_bfloat16 hi = __float2bfloat16(vv[j]);
                float rem = vv[j] - __bfloat162float(hi);
                Bh[n * ASTR + kr] = hi;
                Bl[n * ASTR + kr] = __float2bfloat16(rem);
            }
        }
        __syncthreads();

        #pragma unroll
        for (int ks = 0; ks < 2; ks++) {       // two k16 steps per BK
            unsigned ah[2][4], al[2][4], bh[4][2], bl[4][2];
            #pragma unroll
            for (int mt = 0; mt < 2; mt++) {
                const int m0 = wr * 32 + mt * 16 + g;
                const int base = m0 * WSTR + ks * 8 + tg;
                ah[mt][0] = pAh[base];
                ah[mt][1] = pAh[base + 8 * WSTR];
                ah[mt][2] = pAh[base + 4];
                ah[mt][3] = pAh[base + 8 * WSTR + 4];
                al[mt][0] = pAl[base];
                al[mt][1] = pAl[base + 8 * WSTR];
                al[mt][2] = pAl[base + 4];
                al[mt][3] = pAl[base + 8 * WSTR + 4];
            }
            #pragma unroll
            for (int nt = 0; nt < 4; nt++) {
                const int n0 = wc * 32 + nt * 8 + g;
                const int base = n0 * WSTR + ks * 8 + tg;
                bh[nt][0] = pBh[base];
                bh[nt][1] = pBh[base + 4];
                bl[nt][0] = pBl[base];
                bl[nt][1] = pBl[base + 4];
            }
            #pragma unroll
            for (int mt = 0; mt < 2; mt++)
                #pragma unroll
                for (int nt = 0; nt < 4; nt++) {
                    MMA16816(acc[mt][nt], ah[mt], bh[nt]);
                    MMA16816(acc[mt][nt], ah[mt], bl[nt]);
                    MMA16816(acc[mt][nt], al[mt], bh[nt]);
                }
        }
        __syncthreads();
    }

    // ---- epilogue ----
    #pragma unroll
    for (int mt = 0; mt < 2; mt++) {
        #pragma unroll
        for (int nt = 0; nt < 4; nt++) {
            const int row = mBase + wr * 32 + mt * 16 + g;
            const int col = nBase + wc * 32 + nt * 8 + tg * 2;
            float2 v0 = make_float2(acc[mt][nt][0], acc[mt][nt][1]);
            float2 v1 = make_float2(acc[mt][nt][2], acc[mt][nt][3]);
            if (bias) {
                const float b0 = bias[col], b1 = bias[col + 1];
                v0.x += b0; v0.y += b1;
                v1.x += b0; v1.y += b1;
            }
            *reinterpret_cast<float2*>(&C[(size_t)row * N + col]) = v0;
            *reinterpret_cast<float2*>(&C[(size_t)(row + 8) * N + col]) = v1;
        }
    }
}

// ---------------- self attention (f32x2 packed math) ----------------
__global__ void __launch_bounds__(128)
self_attn_kernel(const float* __restrict__ mask) {
    __shared__ float Ks[NTOK][HDIM];
    __shared__ float Vs[NTOK][HDIM];
    const int h = blockIdx.x, b = blockIdx.y;
    const int t = threadIdx.x;
    const float* base = g_qkv + (size_t)b * NTOK * QKVC;

    {
        const int d = t & 31, r0 = t >> 5;
        #pragma unroll
        for (int i = 0; i < 32; i++) {
            const int row = r0 + i * 4;
            Ks[row][d] = base[row * QKVC + DIMC     + h * HDIM + d];
            Vs[row][d] = base[row * QKVC + 2 * DIMC + h * HDIM + d];
        }
    }
    u64 q2[16];
    {
        const ulonglong2* qp = reinterpret_cast<const ulonglong2*>(base + t * QKVC + h * HDIM);
        const u64 sc = pack2(SCALE, SCALE);
        #pragma unroll
        for (int i = 0; i < 8; i++) {
            ulonglong2 qv = qp[i];
            q2[2 * i]     = mul2(qv.x, sc);
            q2[2 * i + 1] = mul2(qv.y, sc);
        }
    }
    __syncthreads();

    const float* brow = g_bias + h * NTOK * NTOK + t * NTOK;
    const float* mrow = mask + (size_t)(b & 63) * NTOK * NTOK + t * NTOK;

    float sum = 0.0f;
    u64 acc2[16];
    const u64 z = pack2(0.f, 0.f);
    #pragma unroll
    for (int i = 0; i < 16; i++) acc2[i] = z;

    #pragma unroll 4
    for (int kk = 0; kk < NTOK; kk++) {
        const ulonglong2* kr = reinterpret_cast<const ulonglong2*>(Ks[kk]);
        u64 s2 = z;
        #pragma unroll
        for (int i = 0; i < 8; i++) {
            ulonglong2 kx = kr[i];
            s2 = fma2(q2[2 * i],     kx.x, s2);
            s2 = fma2(q2[2 * i + 1], kx.y, s2);
        }
        float2 sp = unpack2(s2);
        const float e = __expf(sp.x + sp.y + brow[kk] + mrow[kk]);
        sum += e;
        const u64 e2 = pack2(e, e);
        const ulonglong2* vr = reinterpret_cast<const ulonglong2*>(Vs[kk]);
        #pragma unroll
        for (int i = 0; i < 8; i++) {
            ulonglong2 vx = vr[i];
            acc2[2 * i]     = fma2(vx.x, e2, acc2[2 * i]);
            acc2[2 * i + 1] = fma2(vx.y, e2, acc2[2 * i + 1]);
        }
    }
    const float inv = 1.0f / sum;
    const u64 inv2 = pack2(inv, inv);
    ulonglong2* orow = reinterpret_cast<ulonglong2*>(g_cat + ((size_t)b * NTOK + t) * CATC + DIMC + h * HDIM);
    #pragma unroll
    for (int i = 0; i < 8; i++) {
        ulonglong2 o;
        o.x = mul2(acc2[2 * i], inv2);
        o.y = mul2(acc2[2 * i + 1], inv2);
        orow[i] = o;
    }
}

// ---------------- mutual cross-half attention (f32x2 packed math) ----------------
__global__ void __launch_bounds__(128)
mutual_attn_kernel(const float* __restrict__ mask) {
    __shared__ float Ks[NTOK][HDIM];
    __shared__ float Vs[NTOK][HDIM];
    const int h = blockIdx.x, b = blockIdx.y;
    const int t = threadIdx.x;
    const float* base = g_qkvm + (size_t)b * NTOK * QKVC;

    {
        const int d = t & 31, r0 = t >> 5;
        #pragma unroll
        for (int i = 0; i < 32; i++) {
            const int row = r0 + i * 4;
            Ks[row][d] = base[row * QKVC + DIMC     + h * HDIM + d];
            Vs[row][d] = base[row * QKVC + 2 * DIMC + h * HDIM + d];
        }
    }
    const int qtok  = (t < 64) ? (64 + t) : (t - 64);
    const int kbase = (t < 64) ? 0 : 64;
    const int mri   = (t < 64) ? t : (t - 64);

    u64 q2[16];
    {
        const ulonglong2* qp = reinterpret_cast<const ulonglong2*>(base + qtok * QKVC + h * HDIM);
        const u64 sc = pack2(SCALE, SCALE);
        #pragma unroll
        for (int i = 0; i < 8; i++) {
            ulonglong2 qv = qp[i];
            q2[2 * i]     = mul2(qv.x, sc);
            q2[2 * i + 1] = mul2(qv.y, sc);
        }
    }
    __syncthreads();

    const float* mrow = mask + (size_t)(b & 63) * NTOK * NTOK + mri * NTOK;

    float sum = 0.0f;
    u64 acc2[16];
    const u64 z = pack2(0.f, 0.f);
    #pragma unroll
    for (int i = 0; i < 16; i++) acc2[i] = z;

    #pragma unroll 4
    for (int kk = 0; kk < 64; kk++) {
        const ulonglong2* kr = reinterpret_cast<const ulonglong2*>(Ks[kbase + kk]);
        u64 s2 = z;
        #pragma unroll
        for (int i = 0; i < 8; i++) {
            ulonglong2 kx = kr[i];
            s2 = fma2(q2[2 * i],     kx.x, s2);
            s2 = fma2(q2[2 * i + 1], kx.y, s2);
        }
        float2 sp = unpack2(s2);
        const float e = __expf(sp.x + sp.y + mrow[kk]);
        sum += e;
        const u64 e2 = pack2(e, e);
        const ulonglong2* vr = reinterpret_cast<const ulonglong2*>(Vs[kbase + kk]);
        #pragma unroll
        for (int i = 0; i < 8; i++) {
            ulonglong2 vx = vr[i];
            acc2[2 * i]     = fma2(vx.x, e2, acc2[2 * i]);
            acc2[2 * i + 1] = fma2(vx.y, e2, acc2[2 * i + 1]);
        }
    }
    const float inv = 1.0f / sum;
    const u64 inv2 = pack2(inv, inv);
    ulonglong2* orow = reinterpret_cast<ulonglong2*>(g_cat + ((size_t)b * NTOK + t) * CATC + h * HDIM);
    #pragma unroll
    for (int i = 0; i < 8; i++) {
        ulonglong2 o;
        o.x = mul2(acc2[2 * i], inv2);
        o.y = mul2(acc2[2 * i + 1], inv2);
        orow[i] = o;
    }
}

// ---------------- launch ----------------
extern "C" void kernel_launch(void* const* d_in, const int* in_sizes, int n_in,
                              void* d_out, int out_size) {
    const float* x      = (const float*)d_in[0];
    const float* mask   = (const float*)d_in[1];
    const float* w_qkv  = (const float*)d_in[2];
    const float* w_qkvm = (const float*)d_in[3];
    const float* w_proj = (const float*)d_in[4];
    const float* b_proj = (const float*)d_in[5];
    const float* rpb    = (const float*)d_in[6];
    const float* posb   = (const float*)d_in[7];
    const int*   relidx = (const int*)  d_in[8];
    float* out = (float*)d_out;

    float *qkv, *qkvm, *cat;
    cudaGetSymbolAddress((void**)&qkv,  g_qkv);
    cudaGetSymbolAddress((void**)&qkvm, g_qkvm);
    cudaGetSymbolAddress((void**)&cat,  g_cat);

    bias_gather_kernel<<<NTOK, NTOK>>>(relidx, rpb);

    gemm_bf16x3_kernel<<<dim3(QKVC / BN, MROWS / BM), 256>>>(x, w_qkv,  nullptr, nullptr, qkv,  MROWS, DIMC, QKVC);
    gemm_bf16x3_kernel<<<dim3(QKVC / BN, MROWS / BM), 256>>>(x, w_qkvm, posb,    nullptr, qkvm, MROWS, DIMC, QKVC);

    self_attn_kernel  <<<dim3(NHEADS, NWIN), 128>>>(mask);
    mutual_attn_kernel<<<dim3(NHEADS, NWIN), 128>>>(mask);

    gemm_bf16x3_kernel<<<dim3(DIMC / BN, MROWS / BM), 256>>>(cat, w_proj, nullptr, b_proj, out, MROWS, CATC, DIMC);
}

// round 3
// speedup vs baseline: 1.7329x; 1.3173x over previous
#include <cuda_runtime.h>
#include <cuda_bf16.h>

// ---------------- problem constants ----------------
#define NWIN   1024
#define NTOK   128
#define DIMC   192
#define NHEADS 6
#define HDIM   32
#define QKVC   576
#define CATC   384
#define MROWS  (NWIN*NTOK)   // 131072
#define SCALE  0.17677669529663687f

// ---------------- device-global scratch ----------------
__device__ float g_qkv [MROWS * QKVC];
__device__ float g_qkvm[MROWS * QKVC];
__device__ float g_bias[NHEADS * NTOK * NTOK];
__device__ float g_bm  [NHEADS * 64 * NTOK * NTOK];      // bias+mask combined, 25MB
__device__ __nv_bfloat16 g_xh [MROWS * DIMC];
__device__ __nv_bfloat16 g_xl [MROWS * DIMC];
__device__ __nv_bfloat16 g_xmh[MROWS * DIMC];
__device__ __nv_bfloat16 g_xml[MROWS * DIMC];
__device__ __nv_bfloat16 g_cath[MROWS * CATC];
__device__ __nv_bfloat16 g_catl[MROWS * CATC];
__device__ __nv_bfloat16 g_wqh[QKVC * DIMC];   // [N][K]
__device__ __nv_bfloat16 g_wql[QKVC * DIMC];
__device__ __nv_bfloat16 g_wmh[QKVC * DIMC];
__device__ __nv_bfloat16 g_wml[QKVC * DIMC];
__device__ __nv_bfloat16 g_wph[DIMC * CATC];   // [192][384]
__device__ __nv_bfloat16 g_wpl[DIMC * CATC];

// ---------------- helpers ----------------
typedef unsigned long long u64;
__device__ __forceinline__ u64 fma2(u64 a, u64 b, u64 c) {
    u64 d; asm("fma.rn.f32x2 %0,%1,%2,%3;" : "=l"(d) : "l"(a), "l"(b), "l"(c)); return d;
}
__device__ __forceinline__ u64 mul2(u64 a, u64 b) {
    u64 d; asm("mul.rn.f32x2 %0,%1,%2;" : "=l"(d) : "l"(a), "l"(b)); return d;
}
__device__ __forceinline__ u64 pack2(float x, float y) {
    u64 d; asm("mov.b64 %0,{%1,%2};" : "=l"(d) : "f"(x), "f"(y)); return d;
}
__device__ __forceinline__ float2 unpack2(u64 v) {
    float2 r; asm("mov.b64 {%0,%1},%2;" : "=f"(r.x), "=f"(r.y) : "l"(v)); return r;
}
// split two fp32 into packed bf16 hi-pair and lo-pair
__device__ __forceinline__ void split2(float a, float b, unsigned &hi, unsigned &lo) {
    __nv_bfloat16 ha = __float2bfloat16(a), hb = __float2bfloat16(b);
    float ra = a - __bfloat162float(ha), rb = b - __bfloat162float(hb);
    hi = (unsigned)__bfloat16_as_ushort(ha) | ((unsigned)__bfloat16_as_ushort(hb) << 16);
    lo = (unsigned)__bfloat16_as_ushort(__float2bfloat16(ra)) |
         ((unsigned)__bfloat16_as_ushort(__float2bfloat16(rb)) << 16);
}

// ---------------- preprocessing kernels ----------------
__global__ void bias_gather_kernel(const int* __restrict__ relidx,
                                   const float* __restrict__ rpb) {
    int i = blockIdx.x, j = threadIdx.x;
    int id = relidx[i * NTOK + j];
    #pragma unroll
    for (int h = 0; h < NHEADS; h++)
        g_bias[h * NTOK * NTOK + i * NTOK + j] = rpb[id * NHEADS + h];
}

// g_bm[h][w][t][kk] = g_bias[h][t][kk] + mask[w][t][kk]
__global__ void bm_kernel(const float* __restrict__ mask) {
    int i = blockIdx.x * 256 + threadIdx.x;            // 6,291,456 total
    int hw = i >> 14, r = i & 16383;
    int h = hw / 64, w = hw - h * 64;
    g_bm[i] = g_bias[h * 16384 + r] + mask[w * 16384 + r];
}

// split x and (x + tiled sine pos) into bf16 hi/lo
__global__ void split_x_kernel(const float* __restrict__ x, const float* __restrict__ posb) {
    int idx = blockIdx.x * 256 + threadIdx.x;          // over M*K/4 = 6,291,456 float4
    float4 xv = reinterpret_cast<const float4*>(x)[idx];
    int m = idx / 48, c4 = idx - m * 48;
    float4 pv = reinterpret_cast<const float4*>(posb)[(m & 63) * 48 + c4];
    uint2 h, l;
    split2(xv.x, xv.y, h.x, l.x);
    split2(xv.z, xv.w, h.y, l.y);
    reinterpret_cast<uint2*>(g_xh)[idx] = h;
    reinterpret_cast<uint2*>(g_xl)[idx] = l;
    float4 mv = make_float4(xv.x + pv.x, xv.y + pv.y, xv.z + pv.z, xv.w + pv.w);
    split2(mv.x, mv.y, h.x, l.x);
    split2(mv.z, mv.w, h.y, l.y);
    reinterpret_cast<uint2*>(g_xmh)[idx] = h;
    reinterpret_cast<uint2*>(g_xml)[idx] = l;
}

// transpose + split: w[K][N] -> oh/ol[N][K]
__global__ void split_w_kernel(const float* __restrict__ w,
                               __nv_bfloat16* __restrict__ oh, __nv_bfloat16* __restrict__ ol,
                               int K, int N) {
    int idx = blockIdx.x * 256 + threadIdx.x;          // N*K
    int n = idx / K, k = idx - n * K;
    float v = w[k * N + n];
    __nv_bfloat16 hi = __float2bfloat16(v);
    oh[idx] = hi;
    ol[idx] = __float2bfloat16(v - __bfloat162float(hi));
}

// ---------------- bf16x3 tensor-core GEMM (pre-split operands) ----------------
// C[M,N] = (Ah+Al)[M,K] @ (Bh+Bl)^T  with B stored [N][K]; 3-term Markidis product.
// Block tile 128x64, BK=32, 256 threads (8 warps, 4x2 grid of 32x32 warp tiles).
#define BM 128
#define BN 64
#define BK 32
#define SSTR 40    // bf16 stride (32 + 8 pad), rows 16B-aligned

#define MMA16816(d, a, b) \
    asm volatile("mma.sync.aligned.m16n8k16.row.col.f32.bf16.bf16.f32 " \
        "{%0,%1,%2,%3}, {%4,%5,%6,%7}, {%8,%9}, {%0,%1,%2,%3};" \
        : "+f"(d[0]), "+f"(d[1]), "+f"(d[2]), "+f"(d[3]) \
        : "r"(a[0]), "r"(a[1]), "r"(a[2]), "r"(a[3]), "r"(b[0]), "r"(b[1]))

__device__ __forceinline__ void ldsm4(unsigned &r0, unsigned &r1, unsigned &r2, unsigned &r3,
                                      const __nv_bfloat16* p) {
    unsigned addr = (unsigned)__cvta_generic_to_shared(p);
    asm volatile("ldmatrix.sync.aligned.m8n8.x4.shared.b16 {%0,%1,%2,%3},[%4];"
                 : "=r"(r0), "=r"(r1), "=r"(r2), "=r"(r3) : "r"(addr));
}

__global__ void __launch_bounds__(256)
gemm_bf16x3_kernel(const __nv_bfloat16* __restrict__ Agh, const __nv_bfloat16* __restrict__ Agl,
                   const __nv_bfloat16* __restrict__ Bgh, const __nv_bfloat16* __restrict__ Bgl,
                   const float* __restrict__ bias, float* __restrict__ C,
                   int M, int K, int N) {
    __shared__ alignas(16) __nv_bfloat16 SAh[BM * SSTR];
    __shared__ alignas(16) __nv_bfloat16 SAl[BM * SSTR];
    __shared__ alignas(16) __nv_bfloat16 SBh[BN * SSTR];
    __shared__ alignas(16) __nv_bfloat16 SBl[BN * SSTR];

    const int tid  = threadIdx.x;
    const int lane = tid & 31, warp = tid >> 5;
    const int wr   = warp >> 1, wc = warp & 1;
    const int mBase = blockIdx.y * BM;
    const int nBase = blockIdx.x * BN;

    // ldmatrix per-lane addresses (constant offsets per warp)
    const int aRowL = (lane & 7) + ((lane >> 3) & 1) * 8;
    const int aColL = (lane >> 4) * 8;
    const int bRowL = (lane & 7) + (lane >> 4) * 8;
    const int bColL = ((lane >> 3) & 1) * 8;

    float acc[2][4][4];
    #pragma unroll
    for (int mt = 0; mt < 2; mt++)
        #pragma unroll
        for (int nt = 0; nt < 4; nt++)
            #pragma unroll
            for (int i = 0; i < 4; i++) acc[mt][nt][i] = 0.0f;

    for (int k0 = 0; k0 < K; k0 += BK) {
        // ---- gmem -> smem: A 128x32 hi/lo (2 uint4 each), B 64x32 hi/lo (1 each) ----
        #pragma unroll
        for (int i = 0; i < 2; i++) {
            const int idx = tid + i * 256;
            const int r = idx >> 2, c = idx & 3;       // r 0..127, c float4-of-8bf16
            const size_t g = (size_t)(mBase + r) * K + k0 + c * 8;
            *reinterpret_cast<uint4*>(&SAh[r * SSTR + c * 8]) = *reinterpret_cast<const uint4*>(&Agh[g]);
            *reinterpret_cast<uint4*>(&SAl[r * SSTR + c * 8]) = *reinterpret_cast<const uint4*>(&Agl[g]);
        }
        {
            const int r = tid >> 2, c = tid & 3;       // r 0..63
            const size_t g = (size_t)(nBase + r) * K + k0 + c * 8;
            *reinterpret_cast<uint4*>(&SBh[r * SSTR + c * 8]) = *reinterpret_cast<const uint4*>(&Bgh[g]);
            *reinterpret_cast<uint4*>(&SBl[r * SSTR + c * 8]) = *reinterpret_cast<const uint4*>(&Bgl[g]);
        }
        __syncthreads();

        #pragma unroll
        for (int ks = 0; ks < 2; ks++) {
            const int kk = ks * 16;
            unsigned ah[2][4], al[2][4], bh[4][2], bl[4][2];
            #pragma unroll
            for (int mt = 0; mt < 2; mt++) {
                const int row = wr * 32 + mt * 16 + aRowL;
                ldsm4(ah[mt][0], ah[mt][1], ah[mt][2], ah[mt][3], &SAh[row * SSTR + kk + aColL]);
                ldsm4(al[mt][0], al[mt][1], al[mt][2], al[mt][3], &SAl[row * SSTR + kk + aColL]);
            }
            #pragma unroll
            for (int np = 0; np < 2; np++) {
                const int row = wc * 32 + np * 16 + bRowL;
                ldsm4(bh[2*np][0], bh[2*np][1], bh[2*np+1][0], bh[2*np+1][1], &SBh[row * SSTR + kk + bColL]);
                ldsm4(bl[2*np][0], bl[2*np][1], bl[2*np+1][0], bl[2*np+1][1], &SBl[row * SSTR + kk + bColL]);
            }
            #pragma unroll
            for (int mt = 0; mt < 2; mt++)
                #pragma unroll
                for (int nt = 0; nt < 4; nt++) {
                    MMA16816(acc[mt][nt], ah[mt], bh[nt]);
                    MMA16816(acc[mt][nt], ah[mt], bl[nt]);
                    MMA16816(acc[mt][nt], al[mt], bh[nt]);
                }
        }
        __syncthreads();
    }

    const int g = lane >> 2, tg = lane & 3;
    #pragma unroll
    for (int mt = 0; mt < 2; mt++)
        #pragma unroll
        for (int nt = 0; nt < 4; nt++) {
            const int row = mBase + wr * 32 + mt * 16 + g;
            const int col = nBase + wc * 32 + nt * 8 + tg * 2;
            float2 v0 = make_float2(acc[mt][nt][0], acc[mt][nt][1]);
            float2 v1 = make_float2(acc[mt][nt][2], acc[mt][nt][3]);
            if (bias) {
                const float b0 = bias[col], b1 = bias[col + 1];
                v0.x += b0; v0.y += b1; v1.x += b0; v1.y += b1;
            }
            *reinterpret_cast<float2*>(&C[(size_t)row * N + col]) = v0;
            *reinterpret_cast<float2*>(&C[(size_t)(row + 8) * N + col]) = v1;
        }
}

// ---------------- attention output writer (fp32 acc -> split bf16 cat) ----------------
__device__ __forceinline__ void write_cat_split(u64* acc2, float inv, size_t row, int coff) {
    const u64 inv2 = pack2(inv, inv);
    unsigned hw[16], lw[16];
    #pragma unroll
    for (int i = 0; i < 16; i++) {
        float2 p = unpack2(mul2(acc2[i], inv2));
        split2(p.x, p.y, hw[i], lw[i]);
    }
    uint4* oh = reinterpret_cast<uint4*>(g_cath + row * CATC + coff);
    uint4* ol = reinterpret_cast<uint4*>(g_catl + row * CATC + coff);
    #pragma unroll
    for (int i = 0; i < 4; i++) {
        oh[i] = make_uint4(hw[4*i], hw[4*i+1], hw[4*i+2], hw[4*i+3]);
        ol[i] = make_uint4(lw[4*i], lw[4*i+1], lw[4*i+2], lw[4*i+3]);
    }
}

// ---------------- self attention ----------------
__global__ void __launch_bounds__(128)
self_attn_kernel() {
    __shared__ float Ks[NTOK][HDIM];
    __shared__ float Vs[NTOK][HDIM];
    const int h = blockIdx.x, b = blockIdx.y;
    const int t = threadIdx.x;
    const float* base = g_qkv + (size_t)b * NTOK * QKVC;

    {
        const int d = t & 31, r0 = t >> 5;
        #pragma unroll
        for (int i = 0; i < 32; i++) {
            const int row = r0 + i * 4;
            Ks[row][d] = base[row * QKVC + DIMC     + h * HDIM + d];
            Vs[row][d] = base[row * QKVC + 2 * DIMC + h * HDIM + d];
        }
    }
    u64 q2[16];
    {
        const ulonglong2* qp = reinterpret_cast<const ulonglong2*>(base + t * QKVC + h * HDIM);
        const u64 sc = pack2(SCALE, SCALE);
        #pragma unroll
        for (int i = 0; i < 8; i++) {
            ulonglong2 qv = qp[i];
            q2[2*i] = mul2(qv.x, sc); q2[2*i+1] = mul2(qv.y, sc);
        }
    }
    __syncthreads();

    const float* bmrow = g_bm + ((size_t)(h * 64 + (b & 63)) * NTOK + t) * NTOK;

    float sum = 0.0f;
    u64 acc2[16];
    const u64 z = pack2(0.f, 0.f);
    #pragma unroll
    for (int i = 0; i < 16; i++) acc2[i] = z;

    #pragma unroll 4
    for (int kk = 0; kk < NTOK; kk++) {
        const ulonglong2* kr = reinterpret_cast<const ulonglong2*>(Ks[kk]);
        u64 s2 = z;
        #pragma unroll
        for (int i = 0; i < 8; i++) {
            ulonglong2 kx = kr[i];
            s2 = fma2(q2[2*i], kx.x, s2);
            s2 = fma2(q2[2*i+1], kx.y, s2);
        }
        float2 sp = unpack2(s2);
        const float e = __expf(sp.x + sp.y + bmrow[kk]);
        sum += e;
        const u64 e2 = pack2(e, e);
        const ulonglong2* vr = reinterpret_cast<const ulonglong2*>(Vs[kk]);
        #pragma unroll
        for (int i = 0; i < 8; i++) {
            ulonglong2 vx = vr[i];
            acc2[2*i]   = fma2(vx.x, e2, acc2[2*i]);
            acc2[2*i+1] = fma2(vx.y, e2, acc2[2*i+1]);
        }
    }
    write_cat_split(acc2, 1.0f / sum, (size_t)b * NTOK + t, DIMC + h * HDIM);
}

// ---------------- mutual cross-half attention ----------------
__global__ void __launch_bounds__(128)
mutual_attn_kernel(const float* __restrict__ mask) {
    __shared__ float Ks[NTOK][HDIM];
    __shared__ float Vs[NTOK][HDIM];
    const int h = blockIdx.x, b = blockIdx.y;
    const int t = threadIdx.x;
    const float* base = g_qkvm + (size_t)b * NTOK * QKVC;

    {
        const int d = t & 31, r0 = t >> 5;
        #pragma unroll
        for (int i = 0; i < 32; i++) {
            const int row = r0 + i * 4;
            Ks[row][d] = base[row * QKVC + DIMC     + h * HDIM + d];
            Vs[row][d] = base[row * QKVC + 2 * DIMC + h * HDIM + d];
        }
    }
    const int qtok  = (t < 64) ? (64 + t) : (t - 64);
    const int kbase = (t < 64) ? 0 : 64;
    const int mri   = (t < 64) ? t : (t - 64);

    u64 q2[16];
    {
        const ulonglong2* qp = reinterpret_cast<const ulonglong2*>(base + qtok * QKVC + h * HDIM);
        const u64 sc = pack2(SCALE, SCALE);
        #pragma unroll
        for (int i = 0; i < 8; i++) {
            ulonglong2 qv = qp[i];
            q2[2*i] = mul2(qv.x, sc); q2[2*i+1] = mul2(qv.y, sc);
        }
    }
    __syncthreads();

    const float* mrow = mask + (size_t)(b & 63) * NTOK * NTOK + mri * NTOK;

    float sum = 0.0f;
    u64 acc2[16];
    const u64 z = pack2(0.f, 0.f);
    #pragma unroll
    for (int i = 0; i < 16; i++) acc2[i] = z;

    #pragma unroll 4
    for (int kk = 0; kk < 64; kk++) {
        const ulonglong2* kr = reinterpret_cast<const ulonglong2*>(Ks[kbase + kk]);
        u64 s2 = z;
        #pragma unroll
        for (int i = 0; i < 8; i++) {
            ulonglong2 kx = kr[i];
            s2 = fma2(q2[2*i], kx.x, s2);
            s2 = fma2(q2[2*i+1], kx.y, s2);
        }
        float2 sp = unpack2(s2);
        const float e = __expf(sp.x + sp.y + mrow[kk]);
        sum += e;
        const u64 e2 = pack2(e, e);
        const ulonglong2* vr = reinterpret_cast<const ulonglong2*>(Vs[kbase + kk]);
        #pragma unroll
        for (int i = 0; i < 8; i++) {
            ulonglong2 vx = vr[i];
            acc2[2*i]   = fma2(vx.x, e2, acc2[2*i]);
            acc2[2*i+1] = fma2(vx.y, e2, acc2[2*i+1]);
        }
    }
    write_cat_split(acc2, 1.0f / sum, (size_t)b * NTOK + t, h * HDIM);
}

// ---------------- launch ----------------
extern "C" void kernel_launch(void* const* d_in, const int* in_sizes, int n_in,
                              void* d_out, int out_size) {
    const float* x      = (const float*)d_in[0];
    const float* mask   = (const float*)d_in[1];
    const float* w_qkv  = (const float*)d_in[2];
    const float* w_qkvm = (const float*)d_in[3];
    const float* w_proj = (const float*)d_in[4];
    const float* b_proj = (const float*)d_in[5];
    const float* rpb    = (const float*)d_in[6];
    const float* posb   = (const float*)d_in[7];
    const int*   relidx = (const int*)  d_in[8];
    float* out = (float*)d_out;

    float *qkv, *qkvm;
    __nv_bfloat16 *xh, *xl, *xmh, *xml, *cath, *catl;
    __nv_bfloat16 *wqh, *wql, *wmh, *wml, *wph, *wpl;
    cudaGetSymbolAddress((void**)&qkv,  g_qkv);
    cudaGetSymbolAddress((void**)&qkvm, g_qkvm);
    cudaGetSymbolAddress((void**)&xh,  g_xh);  cudaGetSymbolAddress((void**)&xl,  g_xl);
    cudaGetSymbolAddress((void**)&xmh, g_xmh); cudaGetSymbolAddress((void**)&xml, g_xml);
    cudaGetSymbolAddress((void**)&cath, g_cath); cudaGetSymbolAddress((void**)&catl, g_catl);
    cudaGetSymbolAddress((void**)&wqh, g_wqh); cudaGetSymbolAddress((void**)&wql, g_wql);
    cudaGetSymbolAddress((void**)&wmh, g_wmh); cudaGetSymbolAddress((void**)&wml, g_wml);
    cudaGetSymbolAddress((void**)&wph, g_wph); cudaGetSymbolAddress((void**)&wpl, g_wpl);

    bias_gather_kernel<<<NTOK, NTOK>>>(relidx, rpb);
    bm_kernel<<<24576, 256>>>(mask);
    split_x_kernel<<<24576, 256>>>(x, posb);
    split_w_kernel<<<(QKVC * DIMC) / 256, 256>>>(w_qkv,  wqh, wql, DIMC, QKVC);
    split_w_kernel<<<(QKVC * DIMC) / 256, 256>>>(w_qkvm, wmh, wml, DIMC, QKVC);
    split_w_kernel<<<(DIMC * CATC) / 256, 256>>>(w_proj, wph, wpl, CATC, DIMC);

    gemm_bf16x3_kernel<<<dim3(QKVC / BN, MROWS / BM), 256>>>(xh,  xl,  wqh, wql, nullptr, qkv,  MROWS, DIMC, QKVC);
    gemm_bf16x3_kernel<<<dim3(QKVC / BN, MROWS / BM), 256>>>(xmh, xml, wmh, wml, nullptr, qkvm, MROWS, DIMC, QKVC);

    self_attn_kernel  <<<dim3(NHEADS, NWIN), 128>>>();
    mutual_attn_kernel<<<dim3(NHEADS, NWIN), 128>>>(mask);

    gemm_bf16x3_kernel<<<dim3(DIMC / BN, MROWS / BM), 256>>>(cath, catl, wph, wpl, b_proj, out, MROWS, CATC, DIMC);
}

// round 4
// speedup vs baseline: 2.5763x; 1.4867x over previous
#include <cuda_runtime.h>
#include <cuda_bf16.h>

// ---------------- problem constants ----------------
#define NWIN   1024
#define NTOK   128
#define DIMC   192
#define NHEADS 6
#define HDIM   32
#define QKVC   576
#define CATC   384
#define MROWS  (NWIN*NTOK)   // 131072
#define SCALE  0.17677669529663687f

// ---------------- device-global scratch ----------------
__device__ float g_bias[NHEADS * NTOK * NTOK];
__device__ float g_bm  [NHEADS * 64 * NTOK * NTOK];
__device__ __nv_bfloat16 g_xh [MROWS * DIMC];
__device__ __nv_bfloat16 g_xl [MROWS * DIMC];
__device__ __nv_bfloat16 g_xmh[MROWS * DIMC];
__device__ __nv_bfloat16 g_xml[MROWS * DIMC];
__device__ __nv_bfloat16 g_qh [MROWS * QKVC];   // self qkv hi/lo (q pre-scaled)
__device__ __nv_bfloat16 g_ql [MROWS * QKVC];
__device__ __nv_bfloat16 g_mh [MROWS * QKVC];   // mutual qkv hi/lo
__device__ __nv_bfloat16 g_ml [MROWS * QKVC];
__device__ __nv_bfloat16 g_cath[MROWS * CATC];
__device__ __nv_bfloat16 g_catl[MROWS * CATC];
__device__ __nv_bfloat16 g_wqh[QKVC * DIMC];
__device__ __nv_bfloat16 g_wql[QKVC * DIMC];
__device__ __nv_bfloat16 g_wmh[QKVC * DIMC];
__device__ __nv_bfloat16 g_wml[QKVC * DIMC];
__device__ __nv_bfloat16 g_wph[DIMC * CATC];
__device__ __nv_bfloat16 g_wpl[DIMC * CATC];

// ---------------- helpers ----------------
__device__ __forceinline__ void split2(float a, float b, unsigned &hi, unsigned &lo) {
    __nv_bfloat16 ha = __float2bfloat16(a), hb = __float2bfloat16(b);
    float ra = a - __bfloat162float(ha), rb = b - __bfloat162float(hb);
    hi = (unsigned)__bfloat16_as_ushort(ha) | ((unsigned)__bfloat16_as_ushort(hb) << 16);
    lo = (unsigned)__bfloat16_as_ushort(__float2bfloat16(ra)) |
         ((unsigned)__bfloat16_as_ushort(__float2bfloat16(rb)) << 16);
}

#define MMA16816(d, a, b) \
    asm volatile("mma.sync.aligned.m16n8k16.row.col.f32.bf16.bf16.f32 " \
        "{%0,%1,%2,%3}, {%4,%5,%6,%7}, {%8,%9}, {%0,%1,%2,%3};" \
        : "+f"((d)[0]), "+f"((d)[1]), "+f"((d)[2]), "+f"((d)[3]) \
        : "r"((a)[0]), "r"((a)[1]), "r"((a)[2]), "r"((a)[3]), "r"((b)[0]), "r"((b)[1]))

__device__ __forceinline__ void ldsm4(unsigned &r0, unsigned &r1, unsigned &r2, unsigned &r3,
                                      const __nv_bfloat16* p) {
    unsigned addr = (unsigned)__cvta_generic_to_shared(p);
    asm volatile("ldmatrix.sync.aligned.m8n8.x4.shared.b16 {%0,%1,%2,%3},[%4];"
                 : "=r"(r0), "=r"(r1), "=r"(r2), "=r"(r3) : "r"(addr));
}
__device__ __forceinline__ void ldsm4t(unsigned &r0, unsigned &r1, unsigned &r2, unsigned &r3,
                                       const __nv_bfloat16* p) {
    unsigned addr = (unsigned)__cvta_generic_to_shared(p);
    asm volatile("ldmatrix.sync.aligned.m8n8.x4.trans.shared.b16 {%0,%1,%2,%3},[%4];"
                 : "=r"(r0), "=r"(r1), "=r"(r2), "=r"(r3) : "r"(addr));
}

// ---------------- preprocessing ----------------
__global__ void bias_gather_kernel(const int* __restrict__ relidx,
                                   const float* __restrict__ rpb) {
    int i = blockIdx.x, j = threadIdx.x;
    int id = relidx[i * NTOK + j];
    #pragma unroll
    for (int h = 0; h < NHEADS; h++)
        g_bias[h * NTOK * NTOK + i * NTOK + j] = rpb[id * NHEADS + h];
}

__global__ void bm_kernel(const float* __restrict__ mask) {
    int i = blockIdx.x * 256 + threadIdx.x;
    int hw = i >> 14, r = i & 16383;
    int h = hw / 64, w = hw - h * 64;
    g_bm[i] = g_bias[h * 16384 + r] + mask[w * 16384 + r];
}

__global__ void split_x_kernel(const float* __restrict__ x, const float* __restrict__ posb) {
    int idx = blockIdx.x * 256 + threadIdx.x;
    float4 xv = reinterpret_cast<const float4*>(x)[idx];
    int m = idx / 48, c4 = idx - m * 48;
    float4 pv = reinterpret_cast<const float4*>(posb)[(m & 63) * 48 + c4];
    uint2 h, l;
    split2(xv.x, xv.y, h.x, l.x);
    split2(xv.z, xv.w, h.y, l.y);
    reinterpret_cast<uint2*>(g_xh)[idx] = h;
    reinterpret_cast<uint2*>(g_xl)[idx] = l;
    float4 mv = make_float4(xv.x + pv.x, xv.y + pv.y, xv.z + pv.z, xv.w + pv.w);
    split2(mv.x, mv.y, h.x, l.x);
    split2(mv.z, mv.w, h.y, l.y);
    reinterpret_cast<uint2*>(g_xmh)[idx] = h;
    reinterpret_cast<uint2*>(g_xml)[idx] = l;
}

// transpose + split; leading `nscale` output-columns get scaled by s (folds q·SCALE)
__global__ void split_w_kernel(const float* __restrict__ w,
                               __nv_bfloat16* __restrict__ oh, __nv_bfloat16* __restrict__ ol,
                               int K, int N, int nscale, float s) {
    int idx = blockIdx.x * 256 + threadIdx.x;
    int n = idx / K, k = idx - n * K;
    float v = w[k * N + n];
    if (n < nscale) v *= s;
    __nv_bfloat16 hi = __float2bfloat16(v);
    oh[idx] = hi;
    ol[idx] = __float2bfloat16(v - __bfloat162float(hi));
}

// ---------------- bf16x3 tensor-core GEMM ----------------
#define BM 128
#define BN 64
#define BK 32
#define SSTR 40

__global__ void __launch_bounds__(256)
gemm_bf16x3_kernel(const __nv_bfloat16* __restrict__ Agh, const __nv_bfloat16* __restrict__ Agl,
                   const __nv_bfloat16* __restrict__ Bgh, const __nv_bfloat16* __restrict__ Bgl,
                   const float* __restrict__ bias, float* __restrict__ C,
                   __nv_bfloat16* __restrict__ Ch, __nv_bfloat16* __restrict__ Cl,
                   int M, int K, int N) {
    __shared__ alignas(16) __nv_bfloat16 SAh[BM * SSTR];
    __shared__ alignas(16) __nv_bfloat16 SAl[BM * SSTR];
    __shared__ alignas(16) __nv_bfloat16 SBh[BN * SSTR];
    __shared__ alignas(16) __nv_bfloat16 SBl[BN * SSTR];

    const int tid  = threadIdx.x;
    const int lane = tid & 31, warp = tid >> 5;
    const int wr   = warp >> 1, wc = warp & 1;
    const int mBase = blockIdx.y * BM;
    const int nBase = blockIdx.x * BN;

    const int aRowL = (lane & 7) + ((lane >> 3) & 1) * 8;
    const int aColL = (lane >> 4) * 8;
    const int bRowL = (lane & 7) + (lane >> 4) * 8;
    const int bColL = ((lane >> 3) & 1) * 8;

    float acc[2][4][4];
    #pragma unroll
    for (int mt = 0; mt < 2; mt++)
        #pragma unroll
        for (int nt = 0; nt < 4; nt++)
            #pragma unroll
            for (int i = 0; i < 4; i++) acc[mt][nt][i] = 0.0f;

    for (int k0 = 0; k0 < K; k0 += BK) {
        #pragma unroll
        for (int i = 0; i < 2; i++) {
            const int idx = tid + i * 256;
            const int r = idx >> 2, c = idx & 3;
            const size_t g = (size_t)(mBase + r) * K + k0 + c * 8;
            *reinterpret_cast<uint4*>(&SAh[r * SSTR + c * 8]) = *reinterpret_cast<const uint4*>(&Agh[g]);
            *reinterpret_cast<uint4*>(&SAl[r * SSTR + c * 8]) = *reinterpret_cast<const uint4*>(&Agl[g]);
        }
        {
            const int r = tid >> 2, c = tid & 3;
            const size_t g = (size_t)(nBase + r) * K + k0 + c * 8;
            *reinterpret_cast<uint4*>(&SBh[r * SSTR + c * 8]) = *reinterpret_cast<const uint4*>(&Bgh[g]);
            *reinterpret_cast<uint4*>(&SBl[r * SSTR + c * 8]) = *reinterpret_cast<const uint4*>(&Bgl[g]);
        }
        __syncthreads();

        #pragma unroll
        for (int ks = 0; ks < 2; ks++) {
            const int kk = ks * 16;
            unsigned ah[2][4], al[2][4], bh[4][2], bl[4][2];
            #pragma unroll
            for (int mt = 0; mt < 2; mt++) {
                const int row = wr * 32 + mt * 16 + aRowL;
                ldsm4(ah[mt][0], ah[mt][1], ah[mt][2], ah[mt][3], &SAh[row * SSTR + kk + aColL]);
                ldsm4(al[mt][0], al[mt][1], al[mt][2], al[mt][3], &SAl[row * SSTR + kk + aColL]);
            }
            #pragma unroll
            for (int np = 0; np < 2; np++) {
                const int row = wc * 32 + np * 16 + bRowL;
                ldsm4(bh[2*np][0], bh[2*np][1], bh[2*np+1][0], bh[2*np+1][1], &SBh[row * SSTR + kk + bColL]);
                ldsm4(bl[2*np][0], bl[2*np][1], bl[2*np+1][0], bl[2*np+1][1], &SBl[row * SSTR + kk + bColL]);
            }
            #pragma unroll
            for (int mt = 0; mt < 2; mt++)
                #pragma unroll
                for (int nt = 0; nt < 4; nt++) {
                    MMA16816(acc[mt][nt], ah[mt], bh[nt]);
                    MMA16816(acc[mt][nt], ah[mt], bl[nt]);
                    MMA16816(acc[mt][nt], al[mt], bh[nt]);
                }
        }
        __syncthreads();
    }

    const int g = lane >> 2, tg = lane & 3;
    #pragma unroll
    for (int mt = 0; mt < 2; mt++)
        #pragma unroll
        for (int nt = 0; nt < 4; nt++) {
            const int row = mBase + wr * 32 + mt * 16 + g;
            const int col = nBase + wc * 32 + nt * 8 + tg * 2;
            if (Ch) {
                unsigned hi, lo;
                split2(acc[mt][nt][0], acc[mt][nt][1], hi, lo);
                *reinterpret_cast<unsigned*>(&Ch[(size_t)row * N + col]) = hi;
                *reinterpret_cast<unsigned*>(&Cl[(size_t)row * N + col]) = lo;
                split2(acc[mt][nt][2], acc[mt][nt][3], hi, lo);
                *reinterpret_cast<unsigned*>(&Ch[(size_t)(row + 8) * N + col]) = hi;
                *reinterpret_cast<unsigned*>(&Cl[(size_t)(row + 8) * N + col]) = lo;
            } else {
                float2 v0 = make_float2(acc[mt][nt][0], acc[mt][nt][1]);
                float2 v1 = make_float2(acc[mt][nt][2], acc[mt][nt][3]);
                if (bias) {
                    const float b0 = bias[col], b1 = bias[col + 1];
                    v0.x += b0; v0.y += b1; v1.x += b0; v1.y += b1;
                }
                *reinterpret_cast<float2*>(&C[(size_t)row * N + col]) = v0;
                *reinterpret_cast<float2*>(&C[(size_t)(row + 8) * N + col]) = v1;
            }
        }
}

// ---------------- MMA self-attention ----------------
// block = (head h, window b); 4 warps x 32 query rows. bf16x3 QK^T and PV.
#define SATT 40
#define ATT_SMEM (6 * NTOK * SATT * sizeof(__nv_bfloat16))   // 61440

__global__ void __launch_bounds__(128)
self_attn_mma() {
    const int h = blockIdx.x, b = blockIdx.y;
    const int tid = threadIdx.x, lane = tid & 31, w = tid >> 5;
    const int g = lane >> 2, tg = lane & 3;
    extern __shared__ __align__(16) __nv_bfloat16 sm[];
    __nv_bfloat16 *Kh = sm + 2 * NTOK * SATT, *Kl = Kh + NTOK * SATT;
    __nv_bfloat16 *Vh = Kl + NTOK * SATT,     *Vl = Vh + NTOK * SATT;
    __nv_bfloat16 *Qh = sm,                   *Ql = sm + NTOK * SATT;

    #pragma unroll
    for (int s = 0; s < 3; s++) {
        __nv_bfloat16* dh = sm + (2 * s) * NTOK * SATT;
        __nv_bfloat16* dl = dh + NTOK * SATT;
        const int off = s * DIMC + h * HDIM;
        #pragma unroll
        for (int i = 0; i < 4; i++) {
            int idx = i * 128 + tid, row = idx >> 2, c = idx & 3;
            size_t gsrc = ((size_t)b * NTOK + row) * QKVC + off + c * 8;
            *reinterpret_cast<uint4*>(&dh[row * SATT + c * 8]) = *reinterpret_cast<const uint4*>(&g_qh[gsrc]);
            *reinterpret_cast<uint4*>(&dl[row * SATT + c * 8]) = *reinterpret_cast<const uint4*>(&g_ql[gsrc]);
        }
    }
    __syncthreads();

    const int aRowL = (lane & 7) + ((lane >> 3) & 1) * 8, aColL = (lane >> 4) * 8;
    const int bRowL = (lane & 7) + (lane >> 4) * 8,       bColL = ((lane >> 3) & 1) * 8;
    const int vRowL = lane & 15,                          vColL = ((lane >> 4) & 1) * 8;

    #pragma unroll
    for (int mt = 0; mt < 2; mt++) {
        const int qrow = w * 32 + mt * 16;
        float S[16][4];
        #pragma unroll
        for (int nt = 0; nt < 16; nt++)
            #pragma unroll
            for (int i = 0; i < 4; i++) S[nt][i] = 0.0f;

        #pragma unroll
        for (int ks = 0; ks < 2; ks++) {
            unsigned ah[4], al[4];
            ldsm4(ah[0], ah[1], ah[2], ah[3], &Qh[(qrow + aRowL) * SATT + ks * 16 + aColL]);
            ldsm4(al[0], al[1], al[2], al[3], &Ql[(qrow + aRowL) * SATT + ks * 16 + aColL]);
            #pragma unroll
            for (int np = 0; np < 8; np++) {
                unsigned bh[4], bl[4];
                ldsm4(bh[0], bh[1], bh[2], bh[3], &Kh[(np * 16 + bRowL) * SATT + ks * 16 + bColL]);
                ldsm4(bl[0], bl[1], bl[2], bl[3], &Kl[(np * 16 + bRowL) * SATT + ks * 16 + bColL]);
                MMA16816(S[2*np],   ah, bh);     MMA16816(S[2*np],   ah, bl);     MMA16816(S[2*np],   al, bh);
                MMA16816(S[2*np+1], ah, bh + 2); MMA16816(S[2*np+1], ah, bl + 2); MMA16816(S[2*np+1], al, bh + 2);
            }
        }

        // softmax (no max-subtract: |logit| bounded ~7)
        float rs0 = 0.f, rs1 = 0.f;
        unsigned ph[16][2], pl[16][2];
        const float* bm0 = g_bm + ((size_t)(h * 64 + (b & 63)) * NTOK + qrow + g) * NTOK;
        #pragma unroll
        for (int nt = 0; nt < 16; nt++) {
            const int col = nt * 8 + tg * 2;
            float2 m0 = *reinterpret_cast<const float2*>(&bm0[col]);
            float2 m1 = *reinterpret_cast<const float2*>(&bm0[8 * NTOK + col]);
            float e0 = __expf(S[nt][0] + m0.x), e1 = __expf(S[nt][1] + m0.y);
            float e2 = __expf(S[nt][2] + m1.x), e3 = __expf(S[nt][3] + m1.y);
            rs0 += e0 + e1; rs1 += e2 + e3;
            split2(e0, e1, ph[nt][0], pl[nt][0]);
            split2(e2, e3, ph[nt][1], pl[nt][1]);
        }
        rs0 += __shfl_xor_sync(0xffffffff, rs0, 1); rs0 += __shfl_xor_sync(0xffffffff, rs0, 2);
        rs1 += __shfl_xor_sync(0xffffffff, rs1, 1); rs1 += __shfl_xor_sync(0xffffffff, rs1, 2);

        // PV
        float o[4][4];
        #pragma unroll
        for (int nt = 0; nt < 4; nt++)
            #pragma unroll
            for (int i = 0; i < 4; i++) o[nt][i] = 0.0f;

        #pragma unroll
        for (int ks = 0; ks < 8; ks++) {
            unsigned vh[8], vl[8];
            ldsm4t(vh[0], vh[1], vh[2], vh[3], &Vh[(ks * 16 + vRowL) * SATT + vColL]);
            ldsm4t(vh[4], vh[5], vh[6], vh[7], &Vh[(ks * 16 + vRowL) * SATT + 16 + vColL]);
            ldsm4t(vl[0], vl[1], vl[2], vl[3], &Vl[(ks * 16 + vRowL) * SATT + vColL]);
            ldsm4t(vl[4], vl[5], vl[6], vl[7], &Vl[(ks * 16 + vRowL) * SATT + 16 + vColL]);
            unsigned a_h[4] = {ph[2*ks][0], ph[2*ks][1], ph[2*ks+1][0], ph[2*ks+1][1]};
            unsigned a_l[4] = {pl[2*ks][0], pl[2*ks][1], pl[2*ks+1][0], pl[2*ks+1][1]};
            #pragma unroll
            for (int nt = 0; nt < 4; nt++) {
                MMA16816(o[nt], a_h, vh + 2 * nt);
                MMA16816(o[nt], a_h, vl + 2 * nt);
                MMA16816(o[nt], a_l, vh + 2 * nt);
            }
        }

        const float i0 = 1.0f / rs0, i1 = 1.0f / rs1;
        const size_t row0 = (size_t)b * NTOK + qrow + g;
        #pragma unroll
        for (int nt = 0; nt < 4; nt++) {
            const int col = DIMC + h * HDIM + nt * 8 + tg * 2;
            unsigned hi, lo;
            split2(o[nt][0] * i0, o[nt][1] * i0, hi, lo);
            *reinterpret_cast<unsigned*>(&g_cath[row0 * CATC + col]) = hi;
            *reinterpret_cast<unsigned*>(&g_catl[row0 * CATC + col]) = lo;
            split2(o[nt][2] * i1, o[nt][3] * i1, hi, lo);
            *reinterpret_cast<unsigned*>(&g_cath[(row0 + 8) * CATC + col]) = hi;
            *reinterpret_cast<unsigned*>(&g_catl[(row0 + 8) * CATC + col]) = lo;
        }
    }
}

// ---------------- MMA mutual cross-half attention ----------------
// warp w: out rows 32w..32w+31; q rows = (w<2 ? 64+32w : 32(w-2)); keys = 64*(w>>1)..+63
__global__ void __launch_bounds__(128)
mutual_attn_mma(const float* __restrict__ mask) {
    const int h = blockIdx.x, b = blockIdx.y;
    const int tid = threadIdx.x, lane = tid & 31, w = tid >> 5;
    const int g = lane >> 2, tg = lane & 3;
    extern __shared__ __align__(16) __nv_bfloat16 sm[];
    __nv_bfloat16 *Kh = sm + 2 * NTOK * SATT, *Kl = Kh + NTOK * SATT;
    __nv_bfloat16 *Vh = Kl + NTOK * SATT,     *Vl = Vh + NTOK * SATT;
    __nv_bfloat16 *Qh = sm,                   *Ql = sm + NTOK * SATT;

    #pragma unroll
    for (int s = 0; s < 3; s++) {
        __nv_bfloat16* dh = sm + (2 * s) * NTOK * SATT;
        __nv_bfloat16* dl = dh + NTOK * SATT;
        const int off = s * DIMC + h * HDIM;
        #pragma unroll
        for (int i = 0; i < 4; i++) {
            int idx = i * 128 + tid, row = idx >> 2, c = idx & 3;
            size_t gsrc = ((size_t)b * NTOK + row) * QKVC + off + c * 8;
            *reinterpret_cast<uint4*>(&dh[row * SATT + c * 8]) = *reinterpret_cast<const uint4*>(&g_mh[gsrc]);
            *reinterpret_cast<uint4*>(&dl[row * SATT + c * 8]) = *reinterpret_cast<const uint4*>(&g_ml[gsrc]);
        }
    }
    __syncthreads();

    const int aRowL = (lane & 7) + ((lane >> 3) & 1) * 8, aColL = (lane >> 4) * 8;
    const int bRowL = (lane & 7) + (lane >> 4) * 8,       bColL = ((lane >> 3) & 1) * 8;
    const int vRowL = lane & 15,                          vColL = ((lane >> 4) & 1) * 8;

    const int qbase = (w < 2) ? (64 + 32 * w) : (32 * (w - 2));
    const int kb    = (w >> 1) * 64;
    const int ob    = 32 * w;

    #pragma unroll
    for (int mt = 0; mt < 2; mt++) {
        const int qrow = qbase + mt * 16;
        float S[8][4];
        #pragma unroll
        for (int nt = 0; nt < 8; nt++)
            #pragma unroll
            for (int i = 0; i < 4; i++) S[nt][i] = 0.0f;

        #pragma unroll
        for (int ks = 0; ks < 2; ks++) {
            unsigned ah[4], al[4];
            ldsm4(ah[0], ah[1], ah[2], ah[3], &Qh[(qrow + aRowL) * SATT + ks * 16 + aColL]);
            ldsm4(al[0], al[1], al[2], al[3], &Ql[(qrow + aRowL) * SATT + ks * 16 + aColL]);
            #pragma unroll
            for (int np = 0; np < 4; np++) {
                unsigned bh[4], bl[4];
                ldsm4(bh[0], bh[1], bh[2], bh[3], &Kh[(kb + np * 16 + bRowL) * SATT + ks * 16 + bColL]);
                ldsm4(bl[0], bl[1], bl[2], bl[3], &Kl[(kb + np * 16 + bRowL) * SATT + ks * 16 + bColL]);
                MMA16816(S[2*np],   ah, bh);     MMA16816(S[2*np],   ah, bl);     MMA16816(S[2*np],   al, bh);
                MMA16816(S[2*np+1], ah, bh + 2); MMA16816(S[2*np+1], ah, bl + 2); MMA16816(S[2*np+1], al, bh + 2);
            }
        }

        float rs0 = 0.f, rs1 = 0.f;
        unsigned ph[8][2], pl[8][2];
        const int mrow = (ob & 63) + mt * 16 + g;
        const float* mk = mask + ((size_t)(b & 63) * NTOK + mrow) * NTOK;
        #pragma unroll
        for (int nt = 0; nt < 8; nt++) {
            const int col = nt * 8 + tg * 2;
            float2 m0 = *reinterpret_cast<const float2*>(&mk[col]);
            float2 m1 = *reinterpret_cast<const float2*>(&mk[8 * NTOK + col]);
            float e0 = __expf(S[nt][0] + m0.x), e1 = __expf(S[nt][1] + m0.y);
            float e2 = __expf(S[nt][2] + m1.x), e3 = __expf(S[nt][3] + m1.y);
            rs0 += e0 + e1; rs1 += e2 + e3;
            split2(e0, e1, ph[nt][0], pl[nt][0]);
            split2(e2, e3, ph[nt][1], pl[nt][1]);
        }
        rs0 += __shfl_xor_sync(0xffffffff, rs0, 1); rs0 += __shfl_xor_sync(0xffffffff, rs0, 2);
        rs1 += __shfl_xor_sync(0xffffffff, rs1, 1); rs1 += __shfl_xor_sync(0xffffffff, rs1, 2);

        float o[4][4];
        #pragma unroll
        for (int nt = 0; nt < 4; nt++)
            #pragma unroll
            for (int i = 0; i < 4; i++) o[nt][i] = 0.0f;

        #pragma unroll
        for (int ks = 0; ks < 4; ks++) {
            unsigned vh[8], vl[8];
            ldsm4t(vh[0], vh[1], vh[2], vh[3], &Vh[(kb + ks * 16 + vRowL) * SATT + vColL]);
            ldsm4t(vh[4], vh[5], vh[6], vh[7], &Vh[(kb + ks * 16 + vRowL) * SATT + 16 + vColL]);
            ldsm4t(vl[0], vl[1], vl[2], vl[3], &Vl[(kb + ks * 16 + vRowL) * SATT + vColL]);
            ldsm4t(vl[4], vl[5], vl[6], vl[7], &Vl[(kb + ks * 16 + vRowL) * SATT + 16 + vColL]);
            unsigned a_h[4] = {ph[2*ks][0], ph[2*ks][1], ph[2*ks+1][0], ph[2*ks+1][1]};
            unsigned a_l[4] = {pl[2*ks][0], pl[2*ks][1], pl[2*ks+1][0], pl[2*ks+1][1]};
            #pragma unroll
            for (int nt = 0; nt < 4; nt++) {
                MMA16816(o[nt], a_h, vh + 2 * nt);
                MMA16816(o[nt], a_h, vl + 2 * nt);
                MMA16816(o[nt], a_l, vh + 2 * nt);
            }
        }

        const float i0 = 1.0f / rs0, i1 = 1.0f / rs1;
        const size_t row0 = (size_t)b * NTOK + ob + mt * 16 + g;
        #pragma unroll
        for (int nt = 0; nt < 4; nt++) {
            const int col = h * HDIM + nt * 8 + tg * 2;
            unsigned hi, lo;
            split2(o[nt][0] * i0, o[nt][1] * i0, hi, lo);
            *reinterpret_cast<unsigned*>(&g_cath[row0 * CATC + col]) = hi;
            *reinterpret_cast<unsigned*>(&g_catl[row0 * CATC + col]) = lo;
            split2(o[nt][2] * i1, o[nt][3] * i1, hi, lo);
            *reinterpret_cast<unsigned*>(&g_cath[(row0 + 8) * CATC + col]) = hi;
            *reinterpret_cast<unsigned*>(&g_catl[(row0 + 8) * CATC + col]) = lo;
        }
    }
}

// ---------------- launch ----------------
extern "C" void kernel_launch(void* const* d_in, const int* in_sizes, int n_in,
                              void* d_out, int out_size) {
    const float* x      = (const float*)d_in[0];
    const float* mask   = (const float*)d_in[1];
    const float* w_qkv  = (const float*)d_in[2];
    const float* w_qkvm = (const float*)d_in[3];
    const float* w_proj = (const float*)d_in[4];
    const float* b_proj = (const float*)d_in[5];
    const float* rpb    = (const float*)d_in[6];
    const float* posb   = (const float*)d_in[7];
    const int*   relidx = (const int*)  d_in[8];
    float* out = (float*)d_out;

    __nv_bfloat16 *xh, *xl, *xmh, *xml, *cath, *catl;
    __nv_bfloat16 *qh, *ql, *mh, *ml;
    __nv_bfloat16 *wqh, *wql, *wmh, *wml, *wph, *wpl;
    cudaGetSymbolAddress((void**)&xh,  g_xh);  cudaGetSymbolAddress((void**)&xl,  g_xl);
    cudaGetSymbolAddress((void**)&xmh, g_xmh); cudaGetSymbolAddress((void**)&xml, g_xml);
    cudaGetSymbolAddress((void**)&qh,  g_qh);  cudaGetSymbolAddress((void**)&ql,  g_ql);
    cudaGetSymbolAddress((void**)&mh,  g_mh);  cudaGetSymbolAddress((void**)&ml,  g_ml);
    cudaGetSymbolAddress((void**)&cath, g_cath); cudaGetSymbolAddress((void**)&catl, g_catl);
    cudaGetSymbolAddress((void**)&wqh, g_wqh); cudaGetSymbolAddress((void**)&wql, g_wql);
    cudaGetSymbolAddress((void**)&wmh, g_wmh); cudaGetSymbolAddress((void**)&wml, g_wml);
    cudaGetSymbolAddress((void**)&wph, g_wph); cudaGetSymbolAddress((void**)&wpl, g_wpl);

    cudaFuncSetAttribute(self_attn_mma,   cudaFuncAttributeMaxDynamicSharedMemorySize, (int)ATT_SMEM);
    cudaFuncSetAttribute(mutual_attn_mma, cudaFuncAttributeMaxDynamicSharedMemorySize, (int)ATT_SMEM);

    bias_gather_kernel<<<NTOK, NTOK>>>(relidx, rpb);
    bm_kernel<<<24576, 256>>>(mask);
    split_x_kernel<<<24576, 256>>>(x, posb);
    split_w_kernel<<<(QKVC * DIMC) / 256, 256>>>(w_qkv,  wqh, wql, DIMC, QKVC, DIMC, SCALE);
    split_w_kernel<<<(QKVC * DIMC) / 256, 256>>>(w_qkvm, wmh, wml, DIMC, QKVC, DIMC, SCALE);
    split_w_kernel<<<(DIMC * CATC) / 256, 256>>>(w_proj, wph, wpl, CATC, DIMC, 0, 1.0f);

    gemm_bf16x3_kernel<<<dim3(QKVC / BN, MROWS / BM), 256>>>(xh,  xl,  wqh, wql, nullptr, nullptr, qh, ql, MROWS, DIMC, QKVC);
    gemm_bf16x3_kernel<<<dim3(QKVC / BN, MROWS / BM), 256>>>(xmh, xml, wmh, wml, nullptr, nullptr, mh, ml, MROWS, DIMC, QKVC);

    self_attn_mma  <<<dim3(NHEADS, NWIN), 128, ATT_SMEM>>>();
    mutual_attn_mma<<<dim3(NHEADS, NWIN), 128, ATT_SMEM>>>(mask);

    gemm_bf16x3_kernel<<<dim3(DIMC / BN, MROWS / BM), 256>>>(cath, catl, wph, wpl, b_proj, out, nullptr, nullptr, MROWS, CATC, DIMC);
}

// round 6
// speedup vs baseline: 2.8090x; 1.0903x over previous
#include <cuda_runtime.h>
#include <cuda_bf16.h>

// ---------------- problem constants ----------------
#define NWIN   1024
#define NTOK   128
#define DIMC   192
#define NHEADS 6
#define HDIM   32
#define QKVC   576
#define CATC   384
#define MROWS  (NWIN*NTOK)
#define SCALE  0.17677669529663687f

// ---------------- device-global scratch ----------------
__device__ float g_bias[NHEADS * NTOK * NTOK];
__device__ float g_bm  [NHEADS * 64 * NTOK * NTOK];
__device__ __nv_bfloat16 g_xh [MROWS * DIMC];
__device__ __nv_bfloat16 g_xl [MROWS * DIMC];
__device__ __nv_bfloat16 g_xmh[MROWS * DIMC];
__device__ __nv_bfloat16 g_xml[MROWS * DIMC];
__device__ __nv_bfloat16 g_qh [MROWS * QKVC];
__device__ __nv_bfloat16 g_ql [MROWS * QKVC];
__device__ __nv_bfloat16 g_mh [MROWS * QKVC];
__device__ __nv_bfloat16 g_ml [MROWS * QKVC];
__device__ __nv_bfloat16 g_cath[MROWS * CATC];
__device__ __nv_bfloat16 g_catl[MROWS * CATC];
__device__ __nv_bfloat16 g_wqh[QKVC * DIMC];
__device__ __nv_bfloat16 g_wql[QKVC * DIMC];
__device__ __nv_bfloat16 g_wmh[QKVC * DIMC];
__device__ __nv_bfloat16 g_wml[QKVC * DIMC];
__device__ __nv_bfloat16 g_wph[DIMC * CATC];
__device__ __nv_bfloat16 g_wpl[DIMC * CATC];

// ---------------- helpers ----------------
__device__ __forceinline__ void split2(float a, float b, unsigned &hi, unsigned &lo) {
    __nv_bfloat16 ha = __float2bfloat16(a), hb = __float2bfloat16(b);
    float ra = a - __bfloat162float(ha), rb = b - __bfloat162float(hb);
    hi = (unsigned)__bfloat16_as_ushort(ha) | ((unsigned)__bfloat16_as_ushort(hb) << 16);
    lo = (unsigned)__bfloat16_as_ushort(__float2bfloat16(ra)) |
         ((unsigned)__bfloat16_as_ushort(__float2bfloat16(rb)) << 16);
}

#define MMA16816(d, a, b) \
    asm volatile("mma.sync.aligned.m16n8k16.row.col.f32.bf16.bf16.f32 " \
        "{%0,%1,%2,%3}, {%4,%5,%6,%7}, {%8,%9}, {%0,%1,%2,%3};" \
        : "+f"((d)[0]), "+f"((d)[1]), "+f"((d)[2]), "+f"((d)[3]) \
        : "r"((a)[0]), "r"((a)[1]), "r"((a)[2]), "r"((a)[3]), "r"((b)[0]), "r"((b)[1]))

__device__ __forceinline__ void ldsm4(unsigned &r0, unsigned &r1, unsigned &r2, unsigned &r3,
                                      const __nv_bfloat16* p) {
    unsigned addr = (unsigned)__cvta_generic_to_shared(p);
    asm volatile("ldmatrix.sync.aligned.m8n8.x4.shared.b16 {%0,%1,%2,%3},[%4];"
                 : "=r"(r0), "=r"(r1), "=r"(r2), "=r"(r3) : "r"(addr));
}
__device__ __forceinline__ void ldsm4t(unsigned &r0, unsigned &r1, unsigned &r2, unsigned &r3,
                                       const __nv_bfloat16* p) {
    unsigned addr = (unsigned)__cvta_generic_to_shared(p);
    asm volatile("ldmatrix.sync.aligned.m8n8.x4.trans.shared.b16 {%0,%1,%2,%3},[%4];"
                 : "=r"(r0), "=r"(r1), "=r"(r2), "=r"(r3) : "r"(addr));
}
__device__ __forceinline__ void cpa16(void* s, const void* g) {
    unsigned sa = (unsigned)__cvta_generic_to_shared(s);
    asm volatile("cp.async.cg.shared.global [%0], [%1], 16;" :: "r"(sa), "l"(g));
}

// ---------------- preprocessing ----------------
__global__ void bias_gather_kernel(const int* __restrict__ relidx,
                                   const float* __restrict__ rpb) {
    int i = blockIdx.x, j = threadIdx.x;
    int id = relidx[i * NTOK + j];
    #pragma unroll
    for (int h = 0; h < NHEADS; h++)
        g_bias[h * NTOK * NTOK + i * NTOK + j] = rpb[id * NHEADS + h];
}

__global__ void bm_kernel(const float* __restrict__ mask) {
    int i = blockIdx.x * 256 + threadIdx.x;
    int hw = i >> 14, r = i & 16383;
    int h = hw / 64, w = hw - h * 64;
    g_bm[i] = g_bias[h * 16384 + r] + mask[w * 16384 + r];
}

__global__ void split_x_kernel(const float* __restrict__ x, const float* __restrict__ posb) {
    int idx = blockIdx.x * 256 + threadIdx.x;
    float4 xv = reinterpret_cast<const float4*>(x)[idx];
    int m = idx / 48, c4 = idx - m * 48;
    float4 pv = reinterpret_cast<const float4*>(posb)[(m & 63) * 48 + c4];
    uint2 h, l;
    split2(xv.x, xv.y, h.x, l.x);
    split2(xv.z, xv.w, h.y, l.y);
    reinterpret_cast<uint2*>(g_xh)[idx] = h;
    reinterpret_cast<uint2*>(g_xl)[idx] = l;
    float4 mv = make_float4(xv.x + pv.x, xv.y + pv.y, xv.z + pv.z, xv.w + pv.w);
    split2(mv.x, mv.y, h.x, l.x);
    split2(mv.z, mv.w, h.y, l.y);
    reinterpret_cast<uint2*>(g_xmh)[idx] = h;
    reinterpret_cast<uint2*>(g_xml)[idx] = l;
}

__global__ void split_w_kernel(const float* __restrict__ w,
                               __nv_bfloat16* __restrict__ oh, __nv_bfloat16* __restrict__ ol,
                               int K, int N, int nscale, float s) {
    int idx = blockIdx.x * 256 + threadIdx.x;
    int n = idx / K, k = idx - n * K;
    float v = w[k * N + n];
    if (n < nscale) v *= s;
    __nv_bfloat16 hi = __float2bfloat16(v);
    oh[idx] = hi;
    ol[idx] = __float2bfloat16(v - __bfloat162float(hi));
}

// ---------------- bf16x3 GEMM, 2-stage cp.async pipeline ----------------
#define BM 128
#define BN 64
#define BK 32
#define SSTR 40
#define GSA (BM * SSTR)
#define GSB (BN * SSTR)
#define GSTG (2 * GSA + 2 * GSB)
#define GEMM_SMEM (2 * GSTG * (int)sizeof(__nv_bfloat16))   // 61440 B

__global__ void __launch_bounds__(256)
gemm_bf16x3_kernel(const __nv_bfloat16* __restrict__ Agh, const __nv_bfloat16* __restrict__ Agl,
                   const __nv_bfloat16* __restrict__ Bgh, const __nv_bfloat16* __restrict__ Bgl,
                   const float* __restrict__ bias, float* __restrict__ C,
                   __nv_bfloat16* __restrict__ Ch, __nv_bfloat16* __restrict__ Cl,
                   int M, int K, int N) {
    extern __shared__ __align__(16) __nv_bfloat16 dsm[];

    const int tid  = threadIdx.x;
    const int lane = tid & 31, warp = tid >> 5;
    const int wr   = warp >> 1, wc = warp & 1;
    const int mBase = blockIdx.y * BM;
    const int nBase = blockIdx.x * BN;

    const int aRowL = (lane & 7) + ((lane >> 3) & 1) * 8;
    const int aColL = (lane >> 4) * 8;
    const int bRowL = (lane & 7) + (lane >> 4) * 8;
    const int bColL = ((lane >> 3) & 1) * 8;

    const int ar = tid >> 2, ac = tid & 3;
    const int br = tid >> 2, bc = tid & 3;

    float acc[2][4][4];
    #pragma unroll
    for (int mt = 0; mt < 2; mt++)
        #pragma unroll
        for (int nt = 0; nt < 4; nt++)
            #pragma unroll
            for (int i = 0; i < 4; i++) acc[mt][nt][i] = 0.0f;

    const int nk = K / BK;

    auto issue = [&](int k0, int st) {
        __nv_bfloat16* sah = dsm + st * GSTG;
        __nv_bfloat16* sal = sah + GSA;
        __nv_bfloat16* sbh = sal + GSA;
        __nv_bfloat16* sbl = sbh + GSB;
        #pragma unroll
        for (int i = 0; i < 2; i++) {
            const int r = ar + i * 64;
            const size_t g = (size_t)(mBase + r) * K + k0 + ac * 8;
            cpa16(&sah[r * SSTR + ac * 8], &Agh[g]);
            cpa16(&sal[r * SSTR + ac * 8], &Agl[g]);
        }
        {
            const size_t g = (size_t)(nBase + br) * K + k0 + bc * 8;
            cpa16(&sbh[br * SSTR + bc * 8], &Bgh[g]);
            cpa16(&sbl[br * SSTR + bc * 8], &Bgl[g]);
        }
        asm volatile("cp.async.commit_group;");
    };

    issue(0, 0);

    for (int it = 0; it < nk; it++) {
        if (it + 1 < nk) {
            issue((it + 1) * BK, (it + 1) & 1);
            asm volatile("cp.async.wait_group 1;");
        } else {
            asm volatile("cp.async.wait_group 0;");
        }
        __syncthreads();

        const __nv_bfloat16* sah = dsm + (it & 1) * GSTG;
        const __nv_bfloat16* sal = sah + GSA;
        const __nv_bfloat16* sbh = sal + GSA;
        const __nv_bfloat16* sbl = sbh + GSB;

        #pragma unroll
        for (int ks = 0; ks < 2; ks++) {
            const int kk = ks * 16;
            unsigned ah[2][4], al[2][4], bh[4][2], bl[4][2];
            #pragma unroll
            for (int mt = 0; mt < 2; mt++) {
                const int row = wr * 32 + mt * 16 + aRowL;
                ldsm4(ah[mt][0], ah[mt][1], ah[mt][2], ah[mt][3], &sah[row * SSTR + kk + aColL]);
                ldsm4(al[mt][0], al[mt][1], al[mt][2], al[mt][3], &sal[row * SSTR + kk + aColL]);
            }
            #pragma unroll
            for (int np = 0; np < 2; np++) {
                const int row = wc * 32 + np * 16 + bRowL;
                ldsm4(bh[2*np][0], bh[2*np][1], bh[2*np+1][0], bh[2*np+1][1], &sbh[row * SSTR + kk + bColL]);
                ldsm4(bl[2*np][0], bl[2*np][1], bl[2*np+1][0], bl[2*np+1][1], &sbl[row * SSTR + kk + bColL]);
            }
            #pragma unroll
            for (int mt = 0; mt < 2; mt++)
                #pragma unroll
                for (int nt = 0; nt < 4; nt++) {
                    MMA16816(acc[mt][nt], ah[mt], bh[nt]);
                    MMA16816(acc[mt][nt], ah[mt], bl[nt]);
                    MMA16816(acc[mt][nt], al[mt], bh[nt]);
                }
        }
        __syncthreads();
    }

    const int g = lane >> 2, tg = lane & 3;
    #pragma unroll
    for (int mt = 0; mt < 2; mt++)
        #pragma unroll
        for (int nt = 0; nt < 4; nt++) {
            const int row = mBase + wr * 32 + mt * 16 + g;
            const int col = nBase + wc * 32 + nt * 8 + tg * 2;
            if (Ch) {
                unsigned hi, lo;
                split2(acc[mt][nt][0], acc[mt][nt][1], hi, lo);
                *reinterpret_cast<unsigned*>(&Ch[(size_t)row * N + col]) = hi;
                *reinterpret_cast<unsigned*>(&Cl[(size_t)row * N + col]) = lo;
                split2(acc[mt][nt][2], acc[mt][nt][3], hi, lo);
                *reinterpret_cast<unsigned*>(&Ch[(size_t)(row + 8) * N + col]) = hi;
                *reinterpret_cast<unsigned*>(&Cl[(size_t)(row + 8) * N + col]) = lo;
            } else {
                float2 v0 = make_float2(acc[mt][nt][0], acc[mt][nt][1]);
                float2 v1 = make_float2(acc[mt][nt][2], acc[mt][nt][3]);
                if (bias) {
                    const float b0 = bias[col], b1 = bias[col + 1];
                    v0.x += b0; v0.y += b1; v1.x += b0; v1.y += b1;
                }
                *reinterpret_cast<float2*>(&C[(size_t)row * N + col]) = v0;
                *reinterpret_cast<float2*>(&C[(size_t)(row + 8) * N + col]) = v1;
            }
        }
}

// ---------------- streaming MMA attention ----------------
#define SATT 40
#define ATT_SMEM (6 * NTOK * SATT * (int)sizeof(__nv_bfloat16))

__device__ __forceinline__ void attn_warp_body(
    const __nv_bfloat16* Qh, const __nv_bfloat16* Ql,
    const __nv_bfloat16* Kh, const __nv_bfloat16* Kl,
    const __nv_bfloat16* Vh, const __nv_bfloat16* Vl,
    int qrow, int kb, int nstrips,
    const float* scores_row0,      // additive logits for out-row g; col index st*16+... (0-based)
    int lane, size_t outRow0, int outCol0)
{
    const int tg = lane & 3;
    const int aRowL = (lane & 7) + ((lane >> 3) & 1) * 8, aColL = (lane >> 4) * 8;
    const int bRowL = (lane & 7) + (lane >> 4) * 8,       bColL = ((lane >> 3) & 1) * 8;
    const int vRowL = lane & 15,                          vColL = ((lane >> 4) & 1) * 8;

    unsigned ah[2][4], al[2][4];
    #pragma unroll
    for (int ks2 = 0; ks2 < 2; ks2++) {
        ldsm4(ah[ks2][0], ah[ks2][1], ah[ks2][2], ah[ks2][3], &Qh[(qrow + aRowL) * SATT + ks2 * 16 + aColL]);
        ldsm4(al[ks2][0], al[ks2][1], al[ks2][2], al[ks2][3], &Ql[(qrow + aRowL) * SATT + ks2 * 16 + aColL]);
    }

    float o[4][4];
    #pragma unroll
    for (int nt = 0; nt < 4; nt++)
        #pragma unroll
        for (int i = 0; i < 4; i++) o[nt][i] = 0.0f;
    float rs0 = 0.f, rs1 = 0.f;

    for (int st = 0; st < nstrips; st++) {
        const int krow = kb + st * 16;
        float S[2][4];
        #pragma unroll
        for (int nt = 0; nt < 2; nt++)
            #pragma unroll
            for (int i = 0; i < 4; i++) S[nt][i] = 0.0f;

        #pragma unroll
        for (int ks2 = 0; ks2 < 2; ks2++) {
            unsigned bh[4], bl[4];
            ldsm4(bh[0], bh[1], bh[2], bh[3], &Kh[(krow + bRowL) * SATT + ks2 * 16 + bColL]);
            ldsm4(bl[0], bl[1], bl[2], bl[3], &Kl[(krow + bRowL) * SATT + ks2 * 16 + bColL]);
            MMA16816(S[0], ah[ks2], bh);     MMA16816(S[0], ah[ks2], bl);     MMA16816(S[0], al[ks2], bh);
            MMA16816(S[1], ah[ks2], bh + 2); MMA16816(S[1], ah[ks2], bl + 2); MMA16816(S[1], al[ks2], bh + 2);
        }

        unsigned ph[4], pl[4];
        #pragma unroll
        for (int nt = 0; nt < 2; nt++) {
            const int col = st * 16 + nt * 8 + tg * 2;
            float2 m0 = *reinterpret_cast<const float2*>(&scores_row0[col]);
            float2 m1 = *reinterpret_cast<const float2*>(&scores_row0[8 * NTOK + col]);
            float e0 = __expf(S[nt][0] + m0.x), e1 = __expf(S[nt][1] + m0.y);
            float e2 = __expf(S[nt][2] + m1.x), e3 = __expf(S[nt][3] + m1.y);
            rs0 += e0 + e1; rs1 += e2 + e3;
            split2(e0, e1, ph[2*nt], pl[2*nt]);
            split2(e2, e3, ph[2*nt+1], pl[2*nt+1]);
        }
        unsigned a_h[4] = {ph[0], ph[1], ph[2], ph[3]};
        unsigned a_l[4] = {pl[0], pl[1], pl[2], pl[3]};

        unsigned vh[8], vl[8];
        ldsm4t(vh[0], vh[1], vh[2], vh[3], &Vh[(krow + vRowL) * SATT + vColL]);
        ldsm4t(vh[4], vh[5], vh[6], vh[7], &Vh[(krow + vRowL) * SATT + 16 + vColL]);
        ldsm4t(vl[0], vl[1], vl[2], vl[3], &Vl[(krow + vRowL) * SATT + vColL]);
        ldsm4t(vl[4], vl[5], vl[6], vl[7], &Vl[(krow + vRowL) * SATT + 16 + vColL]);
        #pragma unroll
        for (int nt = 0; nt < 4; nt++) {
            MMA16816(o[nt], a_h, vh + 2 * nt);
            MMA16816(o[nt], a_h, vl + 2 * nt);
            MMA16816(o[nt], a_l, vh + 2 * nt);
        }
    }

    rs0 += __shfl_xor_sync(0xffffffff, rs0, 1); rs0 += __shfl_xor_sync(0xffffffff, rs0, 2);
    rs1 += __shfl_xor_sync(0xffffffff, rs1, 1); rs1 += __shfl_xor_sync(0xffffffff, rs1, 2);
    const float i0 = 1.0f / rs0, i1 = 1.0f / rs1;

    #pragma unroll
    for (int nt = 0; nt < 4; nt++) {
        const int col = outCol0 + nt * 8 + tg * 2;
        unsigned hi, lo;
        split2(o[nt][0] * i0, o[nt][1] * i0, hi, lo);
        *reinterpret_cast<unsigned*>(&g_cath[outRow0 * CATC + col]) = hi;
        *reinterpret_cast<unsigned*>(&g_catl[outRow0 * CATC + col]) = lo;
        split2(o[nt][2] * i1, o[nt][3] * i1, hi, lo);
        *reinterpret_cast<unsigned*>(&g_cath[(outRow0 + 8) * CATC + col]) = hi;
        *reinterpret_cast<unsigned*>(&g_catl[(outRow0 + 8) * CATC + col]) = lo;
    }
}

__device__ __forceinline__ void load_qkv_tiles(__nv_bfloat16* sm, int b, int h, int tid,
                                               const __nv_bfloat16* srch, const __nv_bfloat16* srcl) {
    #pragma unroll
    for (int s = 0; s < 3; s++) {
        __nv_bfloat16* dh = sm + (2 * s) * NTOK * SATT;
        __nv_bfloat16* dl = dh + NTOK * SATT;
        const int off = s * DIMC + h * HDIM;
        #pragma unroll
        for (int i = 0; i < 2; i++) {
            int idx = i * 256 + tid, row = idx >> 2, c = idx & 3;
            size_t gsrc = ((size_t)b * NTOK + row) * QKVC + off + c * 8;
            *reinterpret_cast<uint4*>(&dh[row * SATT + c * 8]) = *reinterpret_cast<const uint4*>(&srch[gsrc]);
            *reinterpret_cast<uint4*>(&dl[row * SATT + c * 8]) = *reinterpret_cast<const uint4*>(&srcl[gsrc]);
        }
    }
}

__global__ void __launch_bounds__(256)
self_attn_mma() {
    const int h = blockIdx.x, b = blockIdx.y;
    const int tid = threadIdx.x, lane = tid & 31, w = tid >> 5;
    extern __shared__ __align__(16) __nv_bfloat16 sm[];
    __nv_bfloat16 *Qh = sm,                   *Ql = sm + NTOK * SATT;
    __nv_bfloat16 *Kh = sm + 2 * NTOK * SATT, *Kl = Kh + NTOK * SATT;
    __nv_bfloat16 *Vh = Kl + NTOK * SATT,     *Vl = Vh + NTOK * SATT;

    load_qkv_tiles(sm, b, h, tid, g_qh, g_ql);
    __syncthreads();

    const int qrow = w * 16;
    const int g = lane >> 2;
    const float* bm0 = g_bm + ((size_t)(h * 64 + (b & 63)) * NTOK + qrow + g) * NTOK;
    attn_warp_body(Qh, Ql, Kh, Kl, Vh, Vl, qrow, 0, 8, bm0, lane,
                   (size_t)b * NTOK + qrow + g, DIMC + h * HDIM);
}

__global__ void __launch_bounds__(256)
mutual_attn_mma(const float* __restrict__ mask) {
    const int h = blockIdx.x, b = blockIdx.y;
    const int tid = threadIdx.x, lane = tid & 31, w = tid >> 5;
    extern __shared__ __align__(16) __nv_bfloat16 sm[];
    __nv_bfloat16 *Qh = sm,                   *Ql = sm + NTOK * SATT;
    __nv_bfloat16 *Kh = sm + 2 * NTOK * SATT, *Kl = Kh + NTOK * SATT;
    __nv_bfloat16 *Vh = Kl + NTOK * SATT,     *Vl = Vh + NTOK * SATT;

    load_qkv_tiles(sm, b, h, tid, g_mh, g_ml);
    __syncthreads();

    // out rows ob..ob+15; q rows: ob<64 -> 64+ob, keys [0,64); else ob-64, keys [64,128)
    const int ob    = w * 16;
    const int qbase = (w < 4) ? (64 + ob) : (ob - 64);
    const int kb    = (w < 4) ? 0 : 64;
    const int mrow0 = (w < 4) ? ob : (ob - 64);
    const int g = lane >> 2;
    // Mask columns are ALWAYS [0,64) for the mutual branch; body indexes cols as st*16+...
    // starting at 0, so pass the UNSHIFTED row base (round-5 bug: spurious -kb shift).
    const float* mk = mask + ((size_t)(b & 63) * NTOK + mrow0 + g) * NTOK;
    attn_warp_body(Qh, Ql, Kh, Kl, Vh, Vl, qbase, kb, 4, mk, lane,
                   (size_t)b * NTOK + ob + g, h * HDIM);
}

// ---------------- launch ----------------
extern "C" void kernel_launch(void* const* d_in, const int* in_sizes, int n_in,
                              void* d_out, int out_size) {
    const float* x      = (const float*)d_in[0];
    const float* mask   = (const float*)d_in[1];
    const float* w_qkv  = (const float*)d_in[2];
    const float* w_qkvm = (const float*)d_in[3];
    const float* w_proj = (const float*)d_in[4];
    const float* b_proj = (const float*)d_in[5];
    const float* rpb    = (const float*)d_in[6];
    const float* posb   = (const float*)d_in[7];
    const int*   relidx = (const int*)  d_in[8];
    float* out = (float*)d_out;

    __nv_bfloat16 *xh, *xl, *xmh, *xml, *cath, *catl;
    __nv_bfloat16 *qh, *ql, *mh, *ml;
    __nv_bfloat16 *wqh, *wql, *wmh, *wml, *wph, *wpl;
    cudaGetSymbolAddress((void**)&xh,  g_xh);  cudaGetSymbolAddress((void**)&xl,  g_xl);
    cudaGetSymbolAddress((void**)&xmh, g_xmh); cudaGetSymbolAddress((void**)&xml, g_xml);
    cudaGetSymbolAddress((void**)&qh,  g_qh);  cudaGetSymbolAddress((void**)&ql,  g_ql);
    cudaGetSymbolAddress((void**)&mh,  g_mh);  cudaGetSymbolAddress((void**)&ml,  g_ml);
    cudaGetSymbolAddress((void**)&cath, g_cath); cudaGetSymbolAddress((void**)&catl, g_catl);
    cudaGetSymbolAddress((void**)&wqh, g_wqh); cudaGetSymbolAddress((void**)&wql, g_wql);
    cudaGetSymbolAddress((void**)&wmh, g_wmh); cudaGetSymbolAddress((void**)&wml, g_wml);
    cudaGetSymbolAddress((void**)&wph, g_wph); cudaGetSymbolAddress((void**)&wpl, g_wpl);

    cudaFuncSetAttribute(gemm_bf16x3_kernel, cudaFuncAttributeMaxDynamicSharedMemorySize, GEMM_SMEM);
    cudaFuncSetAttribute(self_attn_mma,   cudaFuncAttributeMaxDynamicSharedMemorySize, ATT_SMEM);
    cudaFuncSetAttribute(mutual_attn_mma, cudaFuncAttributeMaxDynamicSharedMemorySize, ATT_SMEM);

    bias_gather_kernel<<<NTOK, NTOK>>>(relidx, rpb);
    bm_kernel<<<24576, 256>>>(mask);
    split_x_kernel<<<24576, 256>>>(x, posb);
    split_w_kernel<<<(QKVC * DIMC) / 256, 256>>>(w_qkv,  wqh, wql, DIMC, QKVC, DIMC, SCALE);
    split_w_kernel<<<(QKVC * DIMC) / 256, 256>>>(w_qkvm, wmh, wml, DIMC, QKVC, DIMC, SCALE);
    split_w_kernel<<<(DIMC * CATC) / 256, 256>>>(w_proj, wph, wpl, CATC, DIMC, 0, 1.0f);

    gemm_bf16x3_kernel<<<dim3(QKVC / BN, MROWS / BM), 256, GEMM_SMEM>>>(xh,  xl,  wqh, wql, nullptr, nullptr, qh, ql, MROWS, DIMC, QKVC);
    gemm_bf16x3_kernel<<<dim3(QKVC / BN, MROWS / BM), 256, GEMM_SMEM>>>(xmh, xml, wmh, wml, nullptr, nullptr, mh, ml, MROWS, DIMC, QKVC);

    self_attn_mma  <<<dim3(NHEADS, NWIN), 256, ATT_SMEM>>>();
    mutual_attn_mma<<<dim3(NHEADS, NWIN), 256, ATT_SMEM>>>(mask);

    gemm_bf16x3_kernel<<<dim3(DIMC / BN, MROWS / BM), 256, GEMM_SMEM>>>(cath, catl, wph, wpl, b_proj, out, nullptr, nullptr, MROWS, CATC, DIMC);
}

// round 7
// speedup vs baseline: 2.9869x; 1.0633x over previous
#include <cuda_runtime.h>
#include <cuda_bf16.h>

// ---------------- problem constants ----------------
#define NWIN   1024
#define NTOK   128
#define DIMC   192
#define NHEADS 6
#define HDIM   32
#define QKVC   576
#define CATC   384
#define MROWS  (NWIN*NTOK)
#define SCALE  0.17677669529663687f

// ---------------- device-global scratch ----------------
__device__ float g_bm  [NHEADS * 64 * NTOK * NTOK];
__device__ __nv_bfloat16 g_xh [MROWS * DIMC];
__device__ __nv_bfloat16 g_xl [MROWS * DIMC];
__device__ __nv_bfloat16 g_xmh[MROWS * DIMC];
__device__ __nv_bfloat16 g_xml[MROWS * DIMC];
__device__ __nv_bfloat16 g_qh [MROWS * QKVC];
__device__ __nv_bfloat16 g_ql [MROWS * QKVC];
__device__ __nv_bfloat16 g_mh [MROWS * QKVC];
__device__ __nv_bfloat16 g_ml [MROWS * QKVC];
__device__ __nv_bfloat16 g_cath[MROWS * CATC];
__device__ __nv_bfloat16 g_catl[MROWS * CATC];
__device__ __nv_bfloat16 g_wqh[QKVC * DIMC];
__device__ __nv_bfloat16 g_wql[QKVC * DIMC];
__device__ __nv_bfloat16 g_wmh[QKVC * DIMC];
__device__ __nv_bfloat16 g_wml[QKVC * DIMC];
__device__ __nv_bfloat16 g_wph[DIMC * CATC];
__device__ __nv_bfloat16 g_wpl[DIMC * CATC];

// ---------------- helpers ----------------
__device__ __forceinline__ void split2(float a, float b, unsigned &hi, unsigned &lo) {
    __nv_bfloat16 ha = __float2bfloat16(a), hb = __float2bfloat16(b);
    float ra = a - __bfloat162float(ha), rb = b - __bfloat162float(hb);
    hi = (unsigned)__bfloat16_as_ushort(ha) | ((unsigned)__bfloat16_as_ushort(hb) << 16);
    lo = (unsigned)__bfloat16_as_ushort(__float2bfloat16(ra)) |
         ((unsigned)__bfloat16_as_ushort(__float2bfloat16(rb)) << 16);
}

#define MMA16816(d, a, b) \
    asm volatile("mma.sync.aligned.m16n8k16.row.col.f32.bf16.bf16.f32 " \
        "{%0,%1,%2,%3}, {%4,%5,%6,%7}, {%8,%9}, {%0,%1,%2,%3};" \
        : "+f"((d)[0]), "+f"((d)[1]), "+f"((d)[2]), "+f"((d)[3]) \
        : "r"((a)[0]), "r"((a)[1]), "r"((a)[2]), "r"((a)[3]), "r"((b)[0]), "r"((b)[1]))

__device__ __forceinline__ void ldsm4(unsigned &r0, unsigned &r1, unsigned &r2, unsigned &r3,
                                      const __nv_bfloat16* p) {
    unsigned addr = (unsigned)__cvta_generic_to_shared(p);
    asm volatile("ldmatrix.sync.aligned.m8n8.x4.shared.b16 {%0,%1,%2,%3},[%4];"
                 : "=r"(r0), "=r"(r1), "=r"(r2), "=r"(r3) : "r"(addr));
}
__device__ __forceinline__ void ldsm4t(unsigned &r0, unsigned &r1, unsigned &r2, unsigned &r3,
                                       const __nv_bfloat16* p) {
    unsigned addr = (unsigned)__cvta_generic_to_shared(p);
    asm volatile("ldmatrix.sync.aligned.m8n8.x4.trans.shared.b16 {%0,%1,%2,%3},[%4];"
                 : "=r"(r0), "=r"(r1), "=r"(r2), "=r"(r3) : "r"(addr));
}
__device__ __forceinline__ void cpa16(void* s, const void* g) {
    unsigned sa = (unsigned)__cvta_generic_to_shared(s);
    asm volatile("cp.async.cg.shared.global [%0], [%1], 16;" :: "r"(sa), "l"(g));
}

// ---------------- preprocessing ----------------
// g_bm[h][w][t][k] = rpb[relidx[t,k]][h] + mask[w][t][k]   (bias gather fused)
__global__ void bm_kernel(const float* __restrict__ mask, const int* __restrict__ relidx,
                          const float* __restrict__ rpb) {
    int i = blockIdx.x * 256 + threadIdx.x;
    int hw = i >> 14, r = i & 16383;
    int h = hw / 64, w = hw - h * 64;
    g_bm[i] = rpb[relidx[r] * NHEADS + h] + mask[w * 16384 + r];
}

__global__ void split_x_kernel(const float* __restrict__ x, const float* __restrict__ posb) {
    int idx = blockIdx.x * 256 + threadIdx.x;
    float4 xv = reinterpret_cast<const float4*>(x)[idx];
    int m = idx / 48, c4 = idx - m * 48;
    float4 pv = reinterpret_cast<const float4*>(posb)[(m & 63) * 48 + c4];
    uint2 h, l;
    split2(xv.x, xv.y, h.x, l.x);
    split2(xv.z, xv.w, h.y, l.y);
    reinterpret_cast<uint2*>(g_xh)[idx] = h;
    reinterpret_cast<uint2*>(g_xl)[idx] = l;
    float4 mv = make_float4(xv.x + pv.x, xv.y + pv.y, xv.z + pv.z, xv.w + pv.w);
    split2(mv.x, mv.y, h.x, l.x);
    split2(mv.z, mv.w, h.y, l.y);
    reinterpret_cast<uint2*>(g_xmh)[idx] = h;
    reinterpret_cast<uint2*>(g_xml)[idx] = l;
}

// all three weight transpose+splits in one launch
__global__ void split_w_all(const float* __restrict__ wq, const float* __restrict__ wm,
                            const float* __restrict__ wp) {
    int idx = blockIdx.x * 256 + threadIdx.x;
    const float* w; __nv_bfloat16 *oh, *ol; int K, N, nscale;
    if (idx < QKVC * DIMC) {
        w = wq; oh = g_wqh; ol = g_wql; K = DIMC; N = QKVC; nscale = DIMC;
    } else if (idx < 2 * QKVC * DIMC) {
        idx -= QKVC * DIMC;
        w = wm; oh = g_wmh; ol = g_wml; K = DIMC; N = QKVC; nscale = DIMC;
    } else {
        idx -= 2 * QKVC * DIMC;
        w = wp; oh = g_wph; ol = g_wpl; K = CATC; N = DIMC; nscale = 0;
    }
    int n = idx / K, k = idx - n * K;
    float v = w[k * N + n];
    if (n < nscale) v *= SCALE;
    __nv_bfloat16 hi = __float2bfloat16(v);
    oh[idx] = hi;
    ol[idx] = __float2bfloat16(v - __bfloat162float(hi));
}

// ---------------- bf16x3 GEMM body, 2-stage cp.async pipeline ----------------
#define BM 128
#define BN 64
#define BK 32
#define SSTR 40
#define GSA (BM * SSTR)
#define GSB (BN * SSTR)
#define GSTG (2 * GSA + 2 * GSB)
#define GEMM_SMEM (2 * GSTG * (int)sizeof(__nv_bfloat16))   // 61440 B

__device__ __forceinline__ void gemm_body(
    const __nv_bfloat16* __restrict__ Agh, const __nv_bfloat16* __restrict__ Agl,
    const __nv_bfloat16* __restrict__ Bgh, const __nv_bfloat16* __restrict__ Bgl,
    const float* __restrict__ bias, float* __restrict__ C,
    __nv_bfloat16* __restrict__ Ch, __nv_bfloat16* __restrict__ Cl,
    int K, int N, int mBase, int nBase, __nv_bfloat16* dsm) {

    const int tid  = threadIdx.x;
    const int lane = tid & 31, warp = tid >> 5;
    const int wr   = warp >> 1, wc = warp & 1;

    const int aRowL = (lane & 7) + ((lane >> 3) & 1) * 8;
    const int aColL = (lane >> 4) * 8;
    const int bRowL = (lane & 7) + (lane >> 4) * 8;
    const int bColL = ((lane >> 3) & 1) * 8;

    const int ar = tid >> 2, ac = tid & 3;
    const int br = tid >> 2, bc = tid & 3;

    float acc[2][4][4];
    #pragma unroll
    for (int mt = 0; mt < 2; mt++)
        #pragma unroll
        for (int nt = 0; nt < 4; nt++)
            #pragma unroll
            for (int i = 0; i < 4; i++) acc[mt][nt][i] = 0.0f;

    const int nk = K / BK;

    auto issue = [&](int k0, int st) {
        __nv_bfloat16* sah = dsm + st * GSTG;
        __nv_bfloat16* sal = sah + GSA;
        __nv_bfloat16* sbh = sal + GSA;
        __nv_bfloat16* sbl = sbh + GSB;
        #pragma unroll
        for (int i = 0; i < 2; i++) {
            const int r = ar + i * 64;
            const size_t g = (size_t)(mBase + r) * K + k0 + ac * 8;
            cpa16(&sah[r * SSTR + ac * 8], &Agh[g]);
            cpa16(&sal[r * SSTR + ac * 8], &Agl[g]);
        }
        {
            const size_t g = (size_t)(nBase + br) * K + k0 + bc * 8;
            cpa16(&sbh[br * SSTR + bc * 8], &Bgh[g]);
            cpa16(&sbl[br * SSTR + bc * 8], &Bgl[g]);
        }
        asm volatile("cp.async.commit_group;");
    };

    issue(0, 0);

    for (int it = 0; it < nk; it++) {
        if (it + 1 < nk) {
            issue((it + 1) * BK, (it + 1) & 1);
            asm volatile("cp.async.wait_group 1;");
        } else {
            asm volatile("cp.async.wait_group 0;");
        }
        __syncthreads();

        const __nv_bfloat16* sah = dsm + (it & 1) * GSTG;
        const __nv_bfloat16* sal = sah + GSA;
        const __nv_bfloat16* sbh = sal + GSA;
        const __nv_bfloat16* sbl = sbh + GSB;

        #pragma unroll
        for (int ks = 0; ks < 2; ks++) {
            const int kk = ks * 16;
            unsigned ah[2][4], al[2][4], bh[4][2], bl[4][2];
            #pragma unroll
            for (int mt = 0; mt < 2; mt++) {
                const int row = wr * 32 + mt * 16 + aRowL;
                ldsm4(ah[mt][0], ah[mt][1], ah[mt][2], ah[mt][3], &sah[row * SSTR + kk + aColL]);
                ldsm4(al[mt][0], al[mt][1], al[mt][2], al[mt][3], &sal[row * SSTR + kk + aColL]);
            }
            #pragma unroll
            for (int np = 0; np < 2; np++) {
                const int row = wc * 32 + np * 16 + bRowL;
                ldsm4(bh[2*np][0], bh[2*np][1], bh[2*np+1][0], bh[2*np+1][1], &sbh[row * SSTR + kk + bColL]);
                ldsm4(bl[2*np][0], bl[2*np][1], bl[2*np+1][0], bl[2*np+1][1], &sbl[row * SSTR + kk + bColL]);
            }
            #pragma unroll
            for (int mt = 0; mt < 2; mt++)
                #pragma unroll
                for (int nt = 0; nt < 4; nt++) {
                    MMA16816(acc[mt][nt], ah[mt], bh[nt]);
                    MMA16816(acc[mt][nt], ah[mt], bl[nt]);
                    MMA16816(acc[mt][nt], al[mt], bh[nt]);
                }
        }
        __syncthreads();
    }

    const int g = lane >> 2, tg = lane & 3;
    #pragma unroll
    for (int mt = 0; mt < 2; mt++)
        #pragma unroll
        for (int nt = 0; nt < 4; nt++) {
            const int row = mBase + wr * 32 + mt * 16 + g;
            const int col = nBase + wc * 32 + nt * 8 + tg * 2;
            if (Ch) {
                unsigned hi, lo;
                split2(acc[mt][nt][0], acc[mt][nt][1], hi, lo);
                *reinterpret_cast<unsigned*>(&Ch[(size_t)row * N + col]) = hi;
                *reinterpret_cast<unsigned*>(&Cl[(size_t)row * N + col]) = lo;
                split2(acc[mt][nt][2], acc[mt][nt][3], hi, lo);
                *reinterpret_cast<unsigned*>(&Ch[(size_t)(row + 8) * N + col]) = hi;
                *reinterpret_cast<unsigned*>(&Cl[(size_t)(row + 8) * N + col]) = lo;
            } else {
                float2 v0 = make_float2(acc[mt][nt][0], acc[mt][nt][1]);
                float2 v1 = make_float2(acc[mt][nt][2], acc[mt][nt][3]);
                if (bias) {
                    const float b0 = bias[col], b1 = bias[col + 1];
                    v0.x += b0; v0.y += b1; v1.x += b0; v1.y += b1;
                }
                *reinterpret_cast<float2*>(&C[(size_t)row * N + col]) = v0;
                *reinterpret_cast<float2*>(&C[(size_t)(row + 8) * N + col]) = v1;
            }
        }
}

// both qkv projections in one launch; blockIdx.z selects operand set
__global__ void __launch_bounds__(256)
gemm_qkv_kernel() {
    extern __shared__ __align__(16) __nv_bfloat16 dsm[];
    const int z = blockIdx.z;
    gemm_body(z ? g_xmh : g_xh, z ? g_xml : g_xl,
              z ? g_wmh : g_wqh, z ? g_wml : g_wql,
              nullptr, nullptr,
              z ? g_mh : g_qh, z ? g_ml : g_ql,
              DIMC, QKVC, blockIdx.y * BM, blockIdx.x * BN, dsm);
}

__global__ void __launch_bounds__(256)
gemm_out_kernel(const float* __restrict__ bias, float* __restrict__ C) {
    extern __shared__ __align__(16) __nv_bfloat16 dsm[];
    gemm_body(g_cath, g_catl, g_wph, g_wpl, bias, C, nullptr, nullptr,
              CATC, DIMC, blockIdx.y * BM, blockIdx.x * BN, dsm);
}

// ---------------- streaming MMA attention (self + mutual fused) ----------------
#define SATT 40
#define ATT_SMEM (4 * NTOK * SATT * (int)sizeof(__nv_bfloat16))   // 40960 B (K/V only)

__global__ void __launch_bounds__(256, 3)
attn_mma(const float* __restrict__ mask) {
    const int h = blockIdx.x, b = blockIdx.y, z = blockIdx.z;
    const int tid = threadIdx.x, lane = tid & 31, w = tid >> 5;
    extern __shared__ __align__(16) __nv_bfloat16 sm[];
    __nv_bfloat16 *Kh = sm,                   *Kl = sm + NTOK * SATT;
    __nv_bfloat16 *Vh = sm + 2 * NTOK * SATT, *Vl = sm + 3 * NTOK * SATT;

    const __nv_bfloat16* srch = z ? g_mh : g_qh;
    const __nv_bfloat16* srcl = z ? g_ml : g_ql;

    // K/V tiles via cp.async (overlaps with Q fragment LDGs below)
    #pragma unroll
    for (int s = 0; s < 2; s++) {
        __nv_bfloat16* dh = sm + (2 * s) * NTOK * SATT;
        __nv_bfloat16* dl = dh + NTOK * SATT;
        const int off = (s + 1) * DIMC + h * HDIM;
        #pragma unroll
        for (int i = 0; i < 2; i++) {
            int idx = i * 256 + tid, row = idx >> 2, c = idx & 3;
            size_t gsrc = ((size_t)b * NTOK + row) * QKVC + off + c * 8;
            cpa16(&dh[row * SATT + c * 8], &srch[gsrc]);
            cpa16(&dl[row * SATT + c * 8], &srcl[gsrc]);
        }
    }
    asm volatile("cp.async.commit_group;");

    const int g = lane >> 2, tg = lane & 3;
    int qbase, kb, nstrips, outCol0, orow_base;
    const float* sc;
    if (z == 0) {
        qbase = w * 16; kb = 0; nstrips = 8; orow_base = qbase;
        sc = g_bm + ((size_t)(h * 64 + (b & 63)) * NTOK + qbase + g) * NTOK;
        outCol0 = DIMC + h * HDIM;
    } else {
        const int ob = w * 16;
        qbase = (w < 4) ? (64 + ob) : (ob - 64);
        kb = (w < 4) ? 0 : 64; nstrips = 4; orow_base = ob;
        const int mrow0 = (w < 4) ? ob : (ob - 64);
        sc = mask + ((size_t)(b & 63) * NTOK + mrow0 + g) * NTOK;   // mask cols always [0,64)
        outCol0 = h * HDIM;
    }

    // Q fragments straight from gmem (deterministic m16n8k16 A layout)
    const __nv_bfloat16* qgh = srch + ((size_t)b * NTOK + qbase) * QKVC + h * HDIM;
    const __nv_bfloat16* qgl = srcl + ((size_t)b * NTOK + qbase) * QKVC + h * HDIM;
    unsigned ah[2][4], al[2][4];
    #pragma unroll
    for (int ks2 = 0; ks2 < 2; ks2++)
        #pragma unroll
        for (int r2 = 0; r2 < 2; r2++) {
            const size_t o0 = (size_t)(g + r2 * 8) * QKVC + ks2 * 16 + tg * 2;
            ah[ks2][r2]     = *reinterpret_cast<const unsigned*>(&qgh[o0]);
            ah[ks2][2 + r2] = *reinterpret_cast<const unsigned*>(&qgh[o0 + 8]);
            al[ks2][r2]     = *reinterpret_cast<const unsigned*>(&qgl[o0]);
            al[ks2][2 + r2] = *reinterpret_cast<const unsigned*>(&qgl[o0 + 8]);
        }

    asm volatile("cp.async.wait_group 0;");
    __syncthreads();

    const int bRowL = (lane & 7) + (lane >> 4) * 8, bColL = ((lane >> 3) & 1) * 8;
    const int vRowL = lane & 15,                    vColL = ((lane >> 4) & 1) * 8;

    float o[4][4];
    #pragma unroll
    for (int nt = 0; nt < 4; nt++)
        #pragma unroll
        for (int i = 0; i < 4; i++) o[nt][i] = 0.0f;
    float rs0 = 0.f, rs1 = 0.f;

    for (int st = 0; st < nstrips; st++) {
        const int krow = kb + st * 16;
        float S[2][4];
        #pragma unroll
        for (int nt = 0; nt < 2; nt++)
            #pragma unroll
            for (int i = 0; i < 4; i++) S[nt][i] = 0.0f;

        #pragma unroll
        for (int ks2 = 0; ks2 < 2; ks2++) {
            unsigned bh[4], bl[4];
            ldsm4(bh[0], bh[1], bh[2], bh[3], &Kh[(krow + bRowL) * SATT + ks2 * 16 + bColL]);
            ldsm4(bl[0], bl[1], bl[2], bl[3], &Kl[(krow + bRowL) * SATT + ks2 * 16 + bColL]);
            MMA16816(S[0], ah[ks2], bh);     MMA16816(S[0], ah[ks2], bl);     MMA16816(S[0], al[ks2], bh);
            MMA16816(S[1], ah[ks2], bh + 2); MMA16816(S[1], ah[ks2], bl + 2); MMA16816(S[1], al[ks2], bh + 2);
        }

        unsigned ph[4], pl[4];
        #pragma unroll
        for (int nt = 0; nt < 2; nt++) {
            const int col = st * 16 + nt * 8 + tg * 2;
            float2 m0 = *reinterpret_cast<const float2*>(&sc[col]);
            float2 m1 = *reinterpret_cast<const float2*>(&sc[8 * NTOK + col]);
            float e0 = __expf(S[nt][0] + m0.x), e1 = __expf(S[nt][1] + m0.y);
            float e2 = __expf(S[nt][2] + m1.x), e3 = __expf(S[nt][3] + m1.y);
            rs0 += e0 + e1; rs1 += e2 + e3;
            split2(e0, e1, ph[2*nt], pl[2*nt]);
            split2(e2, e3, ph[2*nt+1], pl[2*nt+1]);
        }

        unsigned vh[8], vl[8];
        ldsm4t(vh[0], vh[1], vh[2], vh[3], &Vh[(krow + vRowL) * SATT + vColL]);
        ldsm4t(vh[4], vh[5], vh[6], vh[7], &Vh[(krow + vRowL) * SATT + 16 + vColL]);
        ldsm4t(vl[0], vl[1], vl[2], vl[3], &Vl[(krow + vRowL) * SATT + vColL]);
        ldsm4t(vl[4], vl[5], vl[6], vl[7], &Vl[(krow + vRowL) * SATT + 16 + vColL]);
        #pragma unroll
        for (int nt = 0; nt < 4; nt++) {
            MMA16816(o[nt], ph, vh + 2 * nt);
            MMA16816(o[nt], ph, vl + 2 * nt);
            MMA16816(o[nt], pl, vh + 2 * nt);
        }
    }

    rs0 += __shfl_xor_sync(0xffffffff, rs0, 1); rs0 += __shfl_xor_sync(0xffffffff, rs0, 2);
    rs1 += __shfl_xor_sync(0xffffffff, rs1, 1); rs1 += __shfl_xor_sync(0xffffffff, rs1, 2);
    const float i0 = 1.0f / rs0, i1 = 1.0f / rs1;

    const size_t outRow0 = (size_t)b * NTOK + orow_base + g;
    #pragma unroll
    for (int nt = 0; nt < 4; nt++) {
        const int col = outCol0 + nt * 8 + tg * 2;
        unsigned hi, lo;
        split2(o[nt][0] * i0, o[nt][1] * i0, hi, lo);
        *reinterpret_cast<unsigned*>(&g_cath[outRow0 * CATC + col]) = hi;
        *reinterpret_cast<unsigned*>(&g_catl[outRow0 * CATC + col]) = lo;
        split2(o[nt][2] * i1, o[nt][3] * i1, hi, lo);
        *reinterpret_cast<unsigned*>(&g_cath[(outRow0 + 8) * CATC + col]) = hi;
        *reinterpret_cast<unsigned*>(&g_catl[(outRow0 + 8) * CATC + col]) = lo;
    }
}

// ---------------- launch ----------------
extern "C" void kernel_launch(void* const* d_in, const int* in_sizes, int n_in,
                              void* d_out, int out_size) {
    const float* x      = (const float*)d_in[0];
    const float* mask   = (const float*)d_in[1];
    const float* w_qkv  = (const float*)d_in[2];
    const float* w_qkvm = (const float*)d_in[3];
    const float* w_proj = (const float*)d_in[4];
    const float* b_proj = (const float*)d_in[5];
    const float* rpb    = (const float*)d_in[6];
    const float* posb   = (const float*)d_in[7];
    const int*   relidx = (const int*)  d_in[8];
    float* out = (float*)d_out;

    cudaFuncSetAttribute(gemm_qkv_kernel, cudaFuncAttributeMaxDynamicSharedMemorySize, GEMM_SMEM);
    cudaFuncSetAttribute(gemm_out_kernel, cudaFuncAttributeMaxDynamicSharedMemorySize, GEMM_SMEM);
    cudaFuncSetAttribute(attn_mma,        cudaFuncAttributeMaxDynamicSharedMemorySize, ATT_SMEM);

    bm_kernel<<<24576, 256>>>(mask, relidx, rpb);
    split_x_kernel<<<24576, 256>>>(x, posb);
    split_w_all<<<(2 * QKVC * DIMC + DIMC * CATC) / 256, 256>>>(w_qkv, w_qkvm, w_proj);

    gemm_qkv_kernel<<<dim3(QKVC / BN, MROWS / BM, 2), 256, GEMM_SMEM>>>();

    attn_mma<<<dim3(NHEADS, NWIN, 2), 256, ATT_SMEM>>>(mask);

    gemm_out_kernel<<<dim3(DIMC / BN, MROWS / BM), 256, GEMM_SMEM>>>(b_proj, out);
}

// round 9
// speedup vs baseline: 6.0943x; 2.0404x over previous
#include <cuda_runtime.h>
#include <cuda_fp16.h>

// ---------------- problem constants ----------------
#define NWIN   1024
#define NTOK   128
#define DIMC   192
#define NHEADS 6
#define HDIM   32
#define QKVC   576
#define CATC   384
#define MROWS  (NWIN*NTOK)
#define SCALE  0.17677669529663687f

// ---------------- device-global scratch ----------------
__device__ float  g_bm  [NHEADS * 64 * NTOK * NTOK];   // bias+mask, fp32 (exp needs abs precision)
__device__ __half g_x16 [MROWS * DIMC];
__device__ __half g_xm16[MROWS * DIMC];
__device__ __half g_q16 [MROWS * QKVC];   // self qkv (q pre-scaled via W fold)
__device__ __half g_m16 [MROWS * QKVC];   // mutual qkv
__device__ __half g_cat16[MROWS * CATC];
__device__ __half g_wq16[QKVC * DIMC];    // [N][K]
__device__ __half g_wm16[QKVC * DIMC];
__device__ __half g_wp16[DIMC * CATC];

// ---------------- helpers ----------------
__device__ __forceinline__ unsigned pkh2(float a, float b) {
    __half2 h = __floats2half2_rn(a, b);
    return *reinterpret_cast<unsigned*>(&h);
}

#define MMAH(d, a, b) \
    asm volatile("mma.sync.aligned.m16n8k16.row.col.f32.f16.f16.f32 " \
        "{%0,%1,%2,%3}, {%4,%5,%6,%7}, {%8,%9}, {%0,%1,%2,%3};" \
        : "+f"((d)[0]), "+f"((d)[1]), "+f"((d)[2]), "+f"((d)[3]) \
        : "r"((a)[0]), "r"((a)[1]), "r"((a)[2]), "r"((a)[3]), "r"((b)[0]), "r"((b)[1]))

__device__ __forceinline__ void ldsm4(unsigned &r0, unsigned &r1, unsigned &r2, unsigned &r3,
                                      const __half* p) {
    unsigned addr = (unsigned)__cvta_generic_to_shared(p);
    asm volatile("ldmatrix.sync.aligned.m8n8.x4.shared.b16 {%0,%1,%2,%3},[%4];"
                 : "=r"(r0), "=r"(r1), "=r"(r2), "=r"(r3) : "r"(addr));
}
__device__ __forceinline__ void ldsm4t(unsigned &r0, unsigned &r1, unsigned &r2, unsigned &r3,
                                       const __half* p) {
    unsigned addr = (unsigned)__cvta_generic_to_shared(p);
    asm volatile("ldmatrix.sync.aligned.m8n8.x4.trans.shared.b16 {%0,%1,%2,%3},[%4];"
                 : "=r"(r0), "=r"(r1), "=r"(r2), "=r"(r3) : "r"(addr));
}
__device__ __forceinline__ void cpa16(void* s, const void* g) {
    unsigned sa = (unsigned)__cvta_generic_to_shared(s);
    asm volatile("cp.async.cg.shared.global [%0], [%1], 16;" :: "r"(sa), "l"(g));
}

// ---------------- preprocessing ----------------
__global__ void bm_kernel(const float* __restrict__ mask, const int* __restrict__ relidx,
                          const float* __restrict__ rpb) {
    int i = blockIdx.x * 256 + threadIdx.x;
    int hw = i >> 14, r = i & 16383;
    int h = hw / 64, w = hw - h * 64;
    g_bm[i] = rpb[relidx[r] * NHEADS + h] + mask[w * 16384 + r];
}

// x and x+posbias -> fp16
__global__ void cvt_x_kernel(const float* __restrict__ x, const float* __restrict__ posb) {
    int idx = blockIdx.x * 256 + threadIdx.x;          // over M*K/4 float4s
    float4 xv = reinterpret_cast<const float4*>(x)[idx];
    int m = idx / 48, c4 = idx - m * 48;
    float4 pv = reinterpret_cast<const float4*>(posb)[(m & 63) * 48 + c4];
    uint2 o;
    o.x = pkh2(xv.x, xv.y); o.y = pkh2(xv.z, xv.w);
    reinterpret_cast<uint2*>(g_x16)[idx] = o;
    o.x = pkh2(xv.x + pv.x, xv.y + pv.y); o.y = pkh2(xv.z + pv.z, xv.w + pv.w);
    reinterpret_cast<uint2*>(g_xm16)[idx] = o;
}

// transpose + convert all three weights; q-columns scaled by SCALE
__global__ void cvt_w_all(const float* __restrict__ wq, const float* __restrict__ wm,
                          const float* __restrict__ wp) {
    int idx = blockIdx.x * 256 + threadIdx.x;
    const float* w; __half* o; int K, N, nscale;
    if (idx < QKVC * DIMC) {
        w = wq; o = g_wq16; K = DIMC; N = QKVC; nscale = DIMC;
    } else if (idx < 2 * QKVC * DIMC) {
        idx -= QKVC * DIMC;
        w = wm; o = g_wm16; K = DIMC; N = QKVC; nscale = DIMC;
    } else {
        idx -= 2 * QKVC * DIMC;
        w = wp; o = g_wp16; K = CATC; N = DIMC; nscale = 0;
    }
    int n = idx / K, k = idx - n * K;
    float v = w[k * N + n];
    if (n < nscale) v *= SCALE;
    o[idx] = __float2half_rn(v);
}

// ---------------- fp16 GEMM, 2-stage cp.async pipeline ----------------
// C[M,N] = A[M,K] @ B^T (B stored [N][K]); tile 128x96, warp tile 32x48.
#define BM 128
#define BN 96
#define BK 32
#define SSTR 40
#define GSA (BM * SSTR)          // 5120 halfs
#define GSB (BN * SSTR)          // 3840 halfs
#define GSTG (GSA + GSB)
#define GEMM_SMEM (2 * GSTG * (int)sizeof(__half))   // 35840 B

__device__ __forceinline__ void gemm_body(
    const __half* __restrict__ A, const __half* __restrict__ B,
    const float* __restrict__ bias, float* __restrict__ C, __half* __restrict__ Ch,
    int K, int N, int mBase, int nBase, __half* dsm) {

    const int tid  = threadIdx.x;
    const int lane = tid & 31, warp = tid >> 5;
    const int wr   = warp >> 1, wc = warp & 1;

    const int aRowL = (lane & 7) + ((lane >> 3) & 1) * 8;
    const int aColL = (lane >> 4) * 8;
    const int bRowL = (lane & 7) + (lane >> 4) * 8;
    const int bColL = ((lane >> 3) & 1) * 8;

    float acc[2][6][4];
    #pragma unroll
    for (int mt = 0; mt < 2; mt++)
        #pragma unroll
        for (int nt = 0; nt < 6; nt++)
            #pragma unroll
            for (int i = 0; i < 4; i++) acc[mt][nt][i] = 0.0f;

    const int nk = K / BK;

    auto issue = [&](int k0, int st) {
        __half* sa = dsm + st * GSTG;
        __half* sb = sa + GSA;
        #pragma unroll
        for (int j = 0; j < 4; j++) {
            int i = tid + j * 256;                    // 896 used of 1024
            if (i < 512) {
                const int r = i >> 2, c = i & 3;
                cpa16(&sa[r * SSTR + c * 8], &A[(size_t)(mBase + r) * K + k0 + c * 8]);
            } else if (i < 896) {
                i -= 512;
                const int r = i >> 2, c = i & 3;
                cpa16(&sb[r * SSTR + c * 8], &B[(size_t)(nBase + r) * K + k0 + c * 8]);
            }
        }
        asm volatile("cp.async.commit_group;");
    };

    issue(0, 0);

    for (int it = 0; it < nk; it++) {
        if (it + 1 < nk) {
            issue((it + 1) * BK, (it + 1) & 1);
            asm volatile("cp.async.wait_group 1;");
        } else {
            asm volatile("cp.async.wait_group 0;");
        }
        __syncthreads();

        const __half* sa = dsm + (it & 1) * GSTG;
        const __half* sb = sa + GSA;

        #pragma unroll
        for (int ks = 0; ks < 2; ks++) {
            const int kk = ks * 16;
            unsigned a[2][4], b[3][4];
            #pragma unroll
            for (int mt = 0; mt < 2; mt++)
                ldsm4(a[mt][0], a[mt][1], a[mt][2], a[mt][3],
                      &sa[(wr * 32 + mt * 16 + aRowL) * SSTR + kk + aColL]);
            #pragma unroll
            for (int np = 0; np < 3; np++)
                ldsm4(b[np][0], b[np][1], b[np][2], b[np][3],
                      &sb[(wc * 48 + np * 16 + bRowL) * SSTR + kk + bColL]);
            #pragma unroll
            for (int mt = 0; mt < 2; mt++)
                #pragma unroll
                for (int np = 0; np < 3; np++) {
                    MMAH(acc[mt][2 * np],     a[mt], b[np]);
                    MMAH(acc[mt][2 * np + 1], a[mt], b[np] + 2);
                }
        }
        __syncthreads();
    }

    const int g = lane >> 2, tg = lane & 3;
    #pragma unroll
    for (int mt = 0; mt < 2; mt++)
        #pragma unroll
        for (int nt = 0; nt < 6; nt++) {
            const int row = mBase + wr * 32 + mt * 16 + g;
            const int col = nBase + wc * 48 + nt * 8 + tg * 2;
            if (Ch) {
                *reinterpret_cast<unsigned*>(&Ch[(size_t)row * N + col]) =
                    pkh2(acc[mt][nt][0], acc[mt][nt][1]);
                *reinterpret_cast<unsigned*>(&Ch[(size_t)(row + 8) * N + col]) =
                    pkh2(acc[mt][nt][2], acc[mt][nt][3]);
            } else {
                const float b0 = bias[col], b1 = bias[col + 1];
                *reinterpret_cast<float2*>(&C[(size_t)row * N + col]) =
                    make_float2(acc[mt][nt][0] + b0, acc[mt][nt][1] + b1);
                *reinterpret_cast<float2*>(&C[(size_t)(row + 8) * N + col]) =
                    make_float2(acc[mt][nt][2] + b0, acc[mt][nt][3] + b1);
            }
        }
}

__global__ void __launch_bounds__(256, 3)
gemm_qkv_kernel() {
    extern __shared__ __align__(16) __half dsm[];
    const int z = blockIdx.z;
    gemm_body(z ? g_xm16 : g_x16, z ? g_wm16 : g_wq16,
              nullptr, nullptr, z ? g_m16 : g_q16,
              DIMC, QKVC, blockIdx.y * BM, blockIdx.x * BN, dsm);
}

__global__ void __launch_bounds__(256, 3)
gemm_out_kernel(const float* __restrict__ bias, float* __restrict__ C) {
    extern __shared__ __align__(16) __half dsm[];
    gemm_body(g_cat16, g_wp16, bias, C, nullptr,
              CATC, DIMC, blockIdx.y * BM, blockIdx.x * BN, dsm);
}

// ---------------- streaming fp16 MMA attention (self + mutual fused) ----------------
#define SATT 40
#define ATT_SMEM (2 * NTOK * SATT * (int)sizeof(__half))   // 20480 B (K/V)

__global__ void __launch_bounds__(256, 3)
attn_mma(const float* __restrict__ mask) {
    const int h = blockIdx.x, b = blockIdx.y, z = blockIdx.z;
    const int tid = threadIdx.x, lane = tid & 31, w = tid >> 5;
    extern __shared__ __align__(16) __half sm[];
    __half *Ks = sm, *Vs = sm + NTOK * SATT;

    const __half* src = z ? g_m16 : g_q16;

    // K/V tiles via cp.async
    #pragma unroll
    for (int s = 0; s < 2; s++) {
        __half* d = sm + s * NTOK * SATT;
        const int off = (s + 1) * DIMC + h * HDIM;
        #pragma unroll
        for (int i = 0; i < 2; i++) {
            int idx = i * 256 + tid, row = idx >> 2, c = idx & 3;
            cpa16(&d[row * SATT + c * 8], &src[((size_t)b * NTOK + row) * QKVC + off + c * 8]);
        }
    }
    asm volatile("cp.async.commit_group;");

    const int g = lane >> 2, tg = lane & 3;
    int qbase, kb, nstrips, outCol0, orow_base;
    const float* sc;
    if (z == 0) {
        qbase = w * 16; kb = 0; nstrips = 8; orow_base = qbase;
        sc = g_bm + ((size_t)(h * 64 + (b & 63)) * NTOK + qbase + g) * NTOK;
        outCol0 = DIMC + h * HDIM;
    } else {
        const int ob = w * 16;
        qbase = (w < 4) ? (64 + ob) : (ob - 64);
        kb = (w < 4) ? 0 : 64; nstrips = 4; orow_base = ob;
        const int mrow0 = (w < 4) ? ob : (ob - 64);
        sc = mask + ((size_t)(b & 63) * NTOK + mrow0 + g) * NTOK;   // mask cols [0,64)
        outCol0 = h * HDIM;
    }

    // Q fragments straight from gmem (m16n8k16 A layout)
    const __half* qg = src + ((size_t)b * NTOK + qbase) * QKVC + h * HDIM;
    unsigned a[2][4];
    #pragma unroll
    for (int ks2 = 0; ks2 < 2; ks2++)
        #pragma unroll
        for (int r2 = 0; r2 < 2; r2++) {
            const size_t o0 = (size_t)(g + r2 * 8) * QKVC + ks2 * 16 + tg * 2;
            a[ks2][r2]     = *reinterpret_cast<const unsigned*>(&qg[o0]);
            a[ks2][2 + r2] = *reinterpret_cast<const unsigned*>(&qg[o0 + 8]);
        }

    asm volatile("cp.async.wait_group 0;");
    __syncthreads();

    const int bRowL = (lane & 7) + (lane >> 4) * 8, bColL = ((lane >> 3) & 1) * 8;
    const int vRowL = lane & 15,                    vColL = ((lane >> 4) & 1) * 8;

    float o[4][4];
    #pragma unroll
    for (int nt = 0; nt < 4; nt++)
        #pragma unroll
        for (int i = 0; i < 4; i++) o[nt][i] = 0.0f;
    float rs0 = 0.f, rs1 = 0.f;

    for (int st = 0; st < nstrips; st++) {
        const int krow = kb + st * 16;
        float S[2][4];
        #pragma unroll
        for (int nt = 0; nt < 2; nt++)
            #pragma unroll
            for (int i = 0; i < 4; i++) S[nt][i] = 0.0f;

        #pragma unroll
        for (int ks2 = 0; ks2 < 2; ks2++) {
            unsigned bk[4];
            ldsm4(bk[0], bk[1], bk[2], bk[3], &Ks[(krow + bRowL) * SATT + ks2 * 16 + bColL]);
            MMAH(S[0], a[ks2], bk);
            MMAH(S[1], a[ks2], bk + 2);
        }

        unsigned pk[4];
        #pragma unroll
        for (int nt = 0; nt < 2; nt++) {
            const int col = st * 16 + nt * 8 + tg * 2;
            float2 m0 = *reinterpret_cast<const float2*>(&sc[col]);
            float2 m1 = *reinterpret_cast<const float2*>(&sc[8 * NTOK + col]);
            float e0 = __expf(S[nt][0] + m0.x), e1 = __expf(S[nt][1] + m0.y);
            float e2 = __expf(S[nt][2] + m1.x), e3 = __expf(S[nt][3] + m1.y);
            rs0 += e0 + e1; rs1 += e2 + e3;
            pk[2 * nt]     = pkh2(e0, e1);
            pk[2 * nt + 1] = pkh2(e2, e3);
        }

        unsigned vh[8];
        ldsm4t(vh[0], vh[1], vh[2], vh[3], &Vs[(krow + vRowL) * SATT + vColL]);
        ldsm4t(vh[4], vh[5], vh[6], vh[7], &Vs[(krow + vRowL) * SATT + 16 + vColL]);
        #pragma unroll
        for (int nt = 0; nt < 4; nt++)
            MMAH(o[nt], pk, vh + 2 * nt);
    }

    rs0 += __shfl_xor_sync(0xffffffff, rs0, 1); rs0 += __shfl_xor_sync(0xffffffff, rs0, 2);
    rs1 += __shfl_xor_sync(0xffffffff, rs1, 1); rs1 += __shfl_xor_sync(0xffffffff, rs1, 2);
    const float i0 = 1.0f / rs0, i1 = 1.0f / rs1;

    const size_t outRow0 = (size_t)b * NTOK + orow_base + g;
    #pragma unroll
    for (int nt = 0; nt < 4; nt++) {
        const int col = outCol0 + nt * 8 + tg * 2;
        *reinterpret_cast<unsigned*>(&g_cat16[outRow0 * CATC + col]) =
            pkh2(o[nt][0] * i0, o[nt][1] * i0);
        *reinterpret_cast<unsigned*>(&g_cat16[(outRow0 + 8) * CATC + col]) =
            pkh2(o[nt][2] * i1, o[nt][3] * i1);
    }
}

// ---------------- launch ----------------
extern "C" void kernel_launch(void* const* d_in, const int* in_sizes, int n_in,
                              void* d_out, int out_size) {
    const float* x      = (const float*)d_in[0];
    const float* mask   = (const float*)d_in[1];
    const float* w_qkv  = (const float*)d_in[2];
    const float* w_qkvm = (const float*)d_in[3];
    const float* w_proj = (const float*)d_in[4];
    const float* b_proj = (const float*)d_in[5];
    const float* rpb    = (const float*)d_in[6];
    const float* posb   = (const float*)d_in[7];
    const int*   relidx = (const int*)  d_in[8];
    float* out = (float*)d_out;

    cudaFuncSetAttribute(gemm_qkv_kernel, cudaFuncAttributeMaxDynamicSharedMemorySize, GEMM_SMEM);
    cudaFuncSetAttribute(gemm_out_kernel, cudaFuncAttributeMaxDynamicSharedMemorySize, GEMM_SMEM);
    cudaFuncSetAttribute(attn_mma,        cudaFuncAttributeMaxDynamicSharedMemorySize, ATT_SMEM);

    bm_kernel<<<24576, 256>>>(mask, relidx, rpb);
    cvt_x_kernel<<<24576, 256>>>(x, posb);
    cvt_w_all<<<(2 * QKVC * DIMC + DIMC * CATC) / 256, 256>>>(w_qkv, w_qkvm, w_proj);

    gemm_qkv_kernel<<<dim3(QKVC / BN, MROWS / BM, 2), 256, GEMM_SMEM>>>();

    attn_mma<<<dim3(NHEADS, NWIN, 2), 256, ATT_SMEM>>>(mask);

    gemm_out_kernel<<<dim3(DIMC / BN, MROWS / BM), 256, GEMM_SMEM>>>(b_proj, out);
}